// round 5
// baseline (speedup 1.0000x reference)
#include <cuda_runtime.h>
#include <math.h>

#define SEQ   512
#define BATCH 128
#define DIN   512
#define HDIM  512
#define G3    1536
#define SCAN_BLOCKS 128

// ---------------- scratch (device globals) ----------------
__device__ float g_gates[(size_t)SEQ * BATCH * G3];      // input gates (~402MB)
// W_h rearranged, k-pair interleaved per 16-hh block:
// g_Whr[by][k2][c][p]  (by 0..31, k2 0..255, c = hh_local*3+gate, p = k parity)
__device__ float g_Whr[32][256][48][2];
__device__ int   g_reset_mode;

// per-bx barrier state (padded to separate cache lines)
__device__ unsigned          g_cnt4[4][64];
__device__ volatile unsigned g_gen4[4][64];

// ---------------- packed fp32x2 FMA (sm_103a) ----------------
__device__ __forceinline__ float2 ffma2(float2 a, float2 b, float2 c) {
    float2 d;
    asm("fma.rn.f32x2 %0, %1, %2, %3;"
        : "=l"(*(unsigned long long*)&d)
        : "l"(*(unsigned long long*)&a),
          "l"(*(unsigned long long*)&b),
          "l"(*(unsigned long long*)&c));
    return d;
}

// ---------------- init + reset dtype sniffing ----------------
__global__ void init_kernel(const unsigned int* __restrict__ r) {
    if (threadIdx.x == 0 && blockIdx.x == 0) {
        bool word_mode = true;
        for (int i = 0; i < 64; i++) {
            unsigned v = r[i];
            if (!(v == 0u || v == 1u || v == 0x3F800000u)) { word_mode = false; break; }
        }
        g_reset_mode = word_mode ? 0 : 2;
#pragma unroll
        for (int i = 0; i < 4; i++) { g_cnt4[i][0] = 0; g_gen4[i][0] = 0; }
    }
}

// ---------------- rearrange W_h ----------------
__global__ void rearrange_wh_kernel(const float* __restrict__ Wh) {
    int idx = blockIdx.x * blockDim.x + threadIdx.x;   // over 32*256*48*2
    if (idx < 32 * 256 * 48 * 2) {
        int p  = idx & 1;
        int c  = (idx >> 1) % 48;
        int k2 = ((idx >> 1) / 48) & 255;
        int by = idx / (2 * 48 * 256);
        int k  = 2 * k2 + p;
        int hh = by * 16 + c / 3;
        int j  = c % 3;
        ((float*)g_Whr)[idx] = Wh[(size_t)k * G3 + j * HDIM + hh];
    }
}

// ---------------- input-gate SGEMM, f32x2 k-pair, 128x64 tile ----------------
#define AS(buf,k2,row) As[((buf)*8 + (k2)) * 130 + (row)]
#define BS(buf,k2,n)   Bs[((buf)*8 + (k2)) * 65  + (n)]
__global__ __launch_bounds__(256)
void gates_gemm_kernel(const float* __restrict__ A,
                       const float* __restrict__ B,
                       const float* __restrict__ bias) {
    __shared__ float2 As[2 * 8 * 130];
    __shared__ float2 Bs[2 * 8 * 65];

    const int N = G3, K = DIN;
    int bn = blockIdx.x, bm = blockIdx.y;
    int t  = threadIdx.x;
    int tx = t & 15, ty = t >> 4;

    float2 acc[8][4];
#pragma unroll
    for (int i = 0; i < 8; i++)
#pragma unroll
        for (int j = 0; j < 4; j++) acc[i][j] = make_float2(0.f, 0.f);

    int ar  = t & 127;
    int akq = (t >> 7) * 4;
    int bnl = t & 63;
    int bks = (t >> 6) * 4;

    const float* Ab = A + (size_t)bm * 128 * K;
    const float* Bb = B + (size_t)bn * 64;

    float4 a0, a1;
    float  bv[4];

    a0 = *(const float4*)(Ab + (size_t)ar * K + akq);
    a1 = *(const float4*)(Ab + (size_t)ar * K + akq + 8);
#pragma unroll
    for (int i = 0; i < 4; i++) bv[i] = Bb[(size_t)(bks + i) * N + bnl];
    AS(0, (akq >> 1),     ar) = make_float2(a0.x, a0.y);
    AS(0, (akq >> 1) + 1, ar) = make_float2(a0.z, a0.w);
    AS(0, (akq >> 1) + 4, ar) = make_float2(a1.x, a1.y);
    AS(0, (akq >> 1) + 5, ar) = make_float2(a1.z, a1.w);
    BS(0, (bks >> 1),     bnl) = make_float2(bv[0], bv[1]);
    BS(0, (bks >> 1) + 1, bnl) = make_float2(bv[2], bv[3]);
    __syncthreads();

    for (int kc = 0; kc < 32; kc++) {
        int cur = kc & 1;
        if (kc < 31) {
            int k0 = (kc + 1) * 16;
            a0 = *(const float4*)(Ab + (size_t)ar * K + k0 + akq);
            a1 = *(const float4*)(Ab + (size_t)ar * K + k0 + akq + 8);
#pragma unroll
            for (int i = 0; i < 4; i++) bv[i] = Bb[(size_t)(k0 + bks + i) * N + bnl];
        }
#pragma unroll
        for (int k2 = 0; k2 < 8; k2++) {
            float2 areg[8], breg[4];
#pragma unroll
            for (int i = 0; i < 8; i++) areg[i] = AS(cur, k2, ty * 8 + i);
#pragma unroll
            for (int j = 0; j < 4; j++) breg[j] = BS(cur, k2, tx + 16 * j);
#pragma unroll
            for (int i = 0; i < 8; i++)
#pragma unroll
                for (int j = 0; j < 4; j++)
                    acc[i][j] = ffma2(areg[i], breg[j], acc[i][j]);
        }
        if (kc < 31) {
            int nb = cur ^ 1;
            AS(nb, (akq >> 1),     ar) = make_float2(a0.x, a0.y);
            AS(nb, (akq >> 1) + 1, ar) = make_float2(a0.z, a0.w);
            AS(nb, (akq >> 1) + 4, ar) = make_float2(a1.x, a1.y);
            AS(nb, (akq >> 1) + 5, ar) = make_float2(a1.z, a1.w);
            BS(nb, (bks >> 1),     bnl) = make_float2(bv[0], bv[1]);
            BS(nb, (bks >> 1) + 1, bnl) = make_float2(bv[2], bv[3]);
        }
        __syncthreads();
    }

    float bsv[4];
#pragma unroll
    for (int j = 0; j < 4; j++) bsv[j] = bias[bn * 64 + tx + 16 * j];
#pragma unroll
    for (int i = 0; i < 8; i++) {
        size_t row = (size_t)bm * 128 + ty * 8 + i;
#pragma unroll
        for (int j = 0; j < 4; j++) {
            int col = bn * 64 + tx + 16 * j;
            g_gates[row * N + col] = acc[i][j].x + acc[i][j].y + bsv[j];
        }
    }
}

// ---------------- per-bx grid barrier (32 blocks each) ----------------
__device__ __forceinline__ void grid_barrier_bx(int bx) {
    __threadfence();
    __syncthreads();
    if (threadIdx.x == 0) {
        unsigned gen = g_gen4[bx][0];
        if (atomicAdd(&g_cnt4[bx][0], 1u) == 31u) {
            g_cnt4[bx][0] = 0;
            __threadfence();
            g_gen4[bx][0] = gen + 1;
        } else {
            while (g_gen4[bx][0] == gen) { __nanosleep(32); }
        }
    }
    __syncthreads();
    __threadfence();
}

// ---------------- persistent scan kernel ----------------
// 128 blocks (bx=bid&3 -> 32 batches, by=bid>>2 -> 16 hh), 256 threads.
// W_h slice (96KB) persistent in SMEM. H read straight from global (L2),
// software-pipelined LDG.128. No per-step smem, no per-step syncthreads.
#define K2STEP(i, hA2, hB2) {                    \
    float2 w0 = wp[(i)*48 + 0];                  \
    float2 w1 = wp[(i)*48 + 1];                  \
    float2 w2 = wp[(i)*48 + 2];                  \
    acc00 = ffma2(hA2, w0, acc00);               \
    acc01 = ffma2(hA2, w1, acc01);               \
    acc02 = ffma2(hA2, w2, acc02);               \
    acc10 = ffma2(hB2, w0, acc10);               \
    acc11 = ffma2(hB2, w1, acc11);               \
    acc12 = ffma2(hB2, w2, acc12); }

#define LOAD_CHUNK(P, c) {                                   \
    const float* pa = hApt + (c) * 16;                       \
    const float* pb = hBpt + (c) * 16;                       \
    P##a0 = *(const float4*)(pa);                            \
    P##a1 = *(const float4*)(pa + 4);                        \
    P##a2 = *(const float4*)(pa + 8);                        \
    P##a3 = *(const float4*)(pa + 12);                       \
    P##b0 = *(const float4*)(pb);                            \
    P##b1 = *(const float4*)(pb + 4);                        \
    P##b2 = *(const float4*)(pb + 8);                        \
    P##b3 = *(const float4*)(pb + 12); }

#define COMPUTE_CHUNK(P) {                                                     \
    K2STEP(0, make_float2(P##a0.x, P##a0.y), make_float2(P##b0.x, P##b0.y));   \
    K2STEP(1, make_float2(P##a0.z, P##a0.w), make_float2(P##b0.z, P##b0.w));   \
    K2STEP(2, make_float2(P##a1.x, P##a1.y), make_float2(P##b1.x, P##b1.y));   \
    K2STEP(3, make_float2(P##a1.z, P##a1.w), make_float2(P##b1.z, P##b1.w));   \
    K2STEP(4, make_float2(P##a2.x, P##a2.y), make_float2(P##b2.x, P##b2.y));   \
    K2STEP(5, make_float2(P##a2.z, P##a2.w), make_float2(P##b2.z, P##b2.w));   \
    K2STEP(6, make_float2(P##a3.x, P##a3.y), make_float2(P##b3.x, P##b3.y));   \
    K2STEP(7, make_float2(P##a3.z, P##a3.w), make_float2(P##b3.z, P##b3.w));   \
    wp += 8 * 48; }

__global__ __launch_bounds__(256)
void scan_kernel(const float* __restrict__ carry,
                 const void*  __restrict__ resets,
                 float* __restrict__ outputs,
                 float* __restrict__ carry_out) {
    extern __shared__ float sm[];   // W slice: 24576 floats (96KB)

    int t   = threadIdx.x;
    int bid = blockIdx.x;
    int bx  = bid & 3, by = bid >> 2;
    int b0  = bx * 32, hh0 = by * 16;
    int tx  = t & 15,  ty = t >> 4;
    int mode = g_reset_mode;
    int hh  = hh0 + tx;
    int bA  = b0 + ty * 2, bB = bA + 1;

    // one-time: W slice into smem (coalesced)
    {
        const float* Wslice = (const float*)g_Whr[by];
        for (int i = t * 4; i < 24576; i += 256 * 4)
            *(float4*)(sm + i) = *(const float4*)(Wslice + i);
    }
    __syncthreads();
    const float2* Wk = (const float2*)sm + tx * 3;

    const unsigned char* rbytes = (const unsigned char*)resets;
    const int*           rints  = (const int*)resets;

    // initial prefetch (step 0)
    float pzA, prA, pnA, pzB, prB, pnB, prmA, prmB;
    {
        size_t gA = (size_t)bA * G3;
        size_t gB = (size_t)bB * G3;
        pzA = g_gates[gA + hh]; prA = g_gates[gA + HDIM + hh]; pnA = g_gates[gA + 2*HDIM + hh];
        pzB = g_gates[gB + hh]; prB = g_gates[gB + HDIM + hh]; pnB = g_gates[gB + 2*HDIM + hh];
        bool rsA = (mode == 0) ? (rints[bA] != 0) : (rbytes[bA] != 0);
        bool rsB = (mode == 0) ? (rints[bB] != 0) : (rbytes[bB] != 0);
        prmA = rsA ? 0.f : 1.f;
        prmB = rsB ? 0.f : 1.f;
    }
    float hpA = carry[(size_t)bA * HDIM + hh];
    float hpB = carry[(size_t)bB * HDIM + hh];

    for (int s = 0; s < SEQ; s++) {
        const float* h_in = (s == 0) ? carry
                                     : outputs + (size_t)(s - 1) * BATCH * HDIM;
        const float* hApt = h_in + (size_t)bA * HDIM;
        const float* hBpt = h_in + (size_t)bB * HDIM;

        float zA = pzA, rA = prA, nA = pnA;
        float zB = pzB, rB = prB, nB = pnB;
        float rmA = prmA, rmB = prmB;

        float2 acc00 = make_float2(0.f, 0.f), acc01 = acc00, acc02 = acc00;
        float2 acc10 = acc00, acc11 = acc00, acc12 = acc00;

        const float2* wp = Wk;
        float4 Xa0, Xa1, Xa2, Xa3, Xb0, Xb1, Xb2, Xb3;
        float4 Ya0, Ya1, Ya2, Ya3, Yb0, Yb1, Yb2, Yb3;

        LOAD_CHUNK(X, 0);
        for (int c = 0; c < 30; c += 2) {
            LOAD_CHUNK(Y, c + 1);
            COMPUTE_CHUNK(X);
            LOAD_CHUNK(X, c + 2);
            COMPUTE_CHUNK(Y);
        }
        LOAD_CHUNK(Y, 31);
        COMPUTE_CHUNK(X);
        COMPUTE_CHUNK(Y);

        // epilogue (mask is k-invariant: apply to the reduced sums)
        {
            float zh = rmA * (acc00.x + acc00.y);
            float rh = rmA * (acc01.x + acc01.y);
            float nh = rmA * (acc02.x + acc02.y);
            float z = 1.f / (1.f + __expf(-(zA + zh)));
            float r = 1.f / (1.f + __expf(-(rA + rh)));
            float n = tanhf(nA + r * nh);
            float hnew = (1.f - z) * n + z * (hpA * rmA);
            outputs[((size_t)s * BATCH + bA) * HDIM + hh] = hnew;
            if (carry_out && s == SEQ - 1) carry_out[(size_t)bA * HDIM + hh] = hnew;
            hpA = hnew;
        }
        {
            float zh = rmB * (acc10.x + acc10.y);
            float rh = rmB * (acc11.x + acc11.y);
            float nh = rmB * (acc12.x + acc12.y);
            float z = 1.f / (1.f + __expf(-(zB + zh)));
            float r = 1.f / (1.f + __expf(-(rB + rh)));
            float n = tanhf(nB + r * nh);
            float hnew = (1.f - z) * n + z * (hpB * rmB);
            outputs[((size_t)s * BATCH + bB) * HDIM + hh] = hnew;
            if (carry_out && s == SEQ - 1) carry_out[(size_t)bB * HDIM + hh] = hnew;
            hpB = hnew;
        }

        // prefetch next step's gates + resets (hidden under barrier)
        {
            int sn = (s + 1 < SEQ) ? s + 1 : s;
            size_t gA = ((size_t)sn * BATCH + bA) * G3;
            size_t gB = ((size_t)sn * BATCH + bB) * G3;
            pzA = g_gates[gA + hh]; prA = g_gates[gA + HDIM + hh]; pnA = g_gates[gA + 2*HDIM + hh];
            pzB = g_gates[gB + hh]; prB = g_gates[gB + HDIM + hh]; pnB = g_gates[gB + 2*HDIM + hh];
            int ri = sn * BATCH;
            bool rsA = (mode == 0) ? (rints[ri + bA] != 0) : (rbytes[ri + bA] != 0);
            bool rsB = (mode == 0) ? (rints[ri + bB] != 0) : (rbytes[ri + bB] != 0);
            prmA = rsA ? 0.f : 1.f;
            prmB = rsB ? 0.f : 1.f;
        }

        if (s < SEQ - 1) grid_barrier_bx(bx);
    }
}

// ---------------- launcher (single stream, sequential) ----------------
extern "C" void kernel_launch(void* const* d_in, const int* in_sizes, int n_in,
                              void* d_out, int out_size) {
    const float* carry = (const float*)d_in[0];
    const float* ins   = (const float*)d_in[1];
    const void*  rsts  = d_in[2];
    const float* W_in  = (const float*)d_in[3];
    const float* b_in  = (const float*)d_in[4];
    const float* W_h   = (const float*)d_in[5];

    float* out = (float*)d_out;
    float* carry_out;
    float* outputs;
    if (out_size == (int)((size_t)SEQ * BATCH * HDIM)) {
        carry_out = nullptr;
        outputs   = out;
    } else {
        carry_out = out;
        outputs   = out + (size_t)BATCH * HDIM;
    }

    const int SMEM_SCAN = 24576 * sizeof(float);
    cudaFuncSetAttribute(scan_kernel,
                         cudaFuncAttributeMaxDynamicSharedMemorySize, SMEM_SCAN);

    init_kernel<<<1, 32>>>((const unsigned int*)rsts);
    rearrange_wh_kernel<<<(32 * 256 * 48 * 2 + 255) / 256, 256>>>(W_h);
    gates_gemm_kernel<<<dim3(G3 / 64, (SEQ * BATCH) / 128), 256>>>(ins, W_in, b_in);
    scan_kernel<<<SCAN_BLOCKS, 256, SMEM_SCAN>>>(carry, rsts, outputs, carry_out);
}

// round 8
// speedup vs baseline: 1.2359x; 1.2359x over previous
#include <cuda_runtime.h>
#include <cuda_bf16.h>
#include <math.h>
#include <stdint.h>

#define SEQ   512
#define BATCH 128
#define DIN   512
#define HDIM  512
#define G3    1536
#define SCAN_BLOCKS 128
#define MROWS (SEQ * BATCH)        // 65536

// ---------------- scratch (device globals) ----------------
__device__ float g_gates[(size_t)SEQ * BATCH * G3];          // ~402MB
__device__ __nv_bfloat16 g_Ahi[(size_t)MROWS * DIN];         // 64MB
__device__ __nv_bfloat16 g_Alo[(size_t)MROWS * DIN];         // 64MB
__device__ __nv_bfloat16 g_Bhi[(size_t)G3 * DIN];            // W_in^T hi [n][k]
__device__ __nv_bfloat16 g_Blo[(size_t)G3 * DIN];            // W_in^T lo [n][k]
__device__ float g_Whr[32][256][48][2];                      // scan W layout
__device__ int   g_reset_mode;

// per-bx barrier state
__device__ unsigned          g_cnt4[4][64];
__device__ volatile unsigned g_gen4[4][64];

// ---------------- packed fp32x2 FMA ----------------
__device__ __forceinline__ float2 ffma2(float2 a, float2 b, float2 c) {
    float2 d;
    asm("fma.rn.f32x2 %0, %1, %2, %3;"
        : "=l"(*(unsigned long long*)&d)
        : "l"(*(unsigned long long*)&a),
          "l"(*(unsigned long long*)&b),
          "l"(*(unsigned long long*)&c));
    return d;
}

// ---------------- mma.sync helpers (plain sm_103-safe) ----------------
__device__ __forceinline__ uint32_t smem_u32(const void* p) {
    return (uint32_t)__cvta_generic_to_shared(p);
}
__device__ __forceinline__ void ldsm4(uint32_t* r, uint32_t addr) {
    asm volatile("ldmatrix.sync.aligned.m8n8.x4.shared.b16 {%0,%1,%2,%3}, [%4];"
                 : "=r"(r[0]), "=r"(r[1]), "=r"(r[2]), "=r"(r[3]) : "r"(addr));
}
__device__ __forceinline__ void mma16816(float* c, const uint32_t* a,
                                         uint32_t b0, uint32_t b1) {
    asm volatile(
        "mma.sync.aligned.m16n8k16.row.col.f32.bf16.bf16.f32 "
        "{%0,%1,%2,%3}, {%4,%5,%6,%7}, {%8,%9}, {%0,%1,%2,%3};"
        : "+f"(c[0]), "+f"(c[1]), "+f"(c[2]), "+f"(c[3])
        : "r"(a[0]), "r"(a[1]), "r"(a[2]), "r"(a[3]), "r"(b0), "r"(b1));
}

// ---------------- init + reset dtype sniffing ----------------
__global__ void init_kernel(const unsigned int* __restrict__ r) {
    if (threadIdx.x == 0 && blockIdx.x == 0) {
        bool word_mode = true;
        for (int i = 0; i < 64; i++) {
            unsigned v = r[i];
            if (!(v == 0u || v == 1u || v == 0x3F800000u)) { word_mode = false; break; }
        }
        g_reset_mode = word_mode ? 0 : 2;
#pragma unroll
        for (int i = 0; i < 4; i++) { g_cnt4[i][0] = 0; g_gen4[i][0] = 0; }
    }
}

// ---------------- hi/lo split prep kernels ----------------
__global__ void prep_a_kernel(const float* __restrict__ ins) {
    size_t base = ((size_t)blockIdx.x * 256 + threadIdx.x) * 4;
    if (base < (size_t)MROWS * DIN) {
        float4 v = *(const float4*)(ins + base);
        float x[4] = {v.x, v.y, v.z, v.w};
#pragma unroll
        for (int i = 0; i < 4; i++) {
            __nv_bfloat16 h = __float2bfloat16(x[i]);
            g_Ahi[base + i] = h;
            g_Alo[base + i] = __float2bfloat16(x[i] - __bfloat162float(h));
        }
    }
}
__global__ void prep_w_kernel(const float* __restrict__ W) {
    int idx = blockIdx.x * 256 + threadIdx.x;   // out idx n*512+k
    if (idx < G3 * DIN) {
        int n = idx >> 9, k = idx & 511;
        float x = W[(size_t)k * G3 + n];
        __nv_bfloat16 h = __float2bfloat16(x);
        g_Bhi[idx] = h;
        g_Blo[idx] = __float2bfloat16(x - __bfloat162float(h));
    }
}

// ---------------- rearrange W_h (scan layout) ----------------
__global__ void rearrange_wh_kernel(const float* __restrict__ Wh) {
    int idx = blockIdx.x * blockDim.x + threadIdx.x;
    if (idx < 32 * 256 * 48 * 2) {
        int p  = idx & 1;
        int c  = (idx >> 1) % 48;
        int k2 = ((idx >> 1) / 48) & 255;
        int by = idx / (2 * 48 * 256);
        int k  = 2 * k2 + p;
        int hh = by * 16 + c / 3;
        int j  = c % 3;
        ((float*)g_Whr)[idx] = Wh[(size_t)k * G3 + j * HDIM + hh];
    }
}

// ---------------- mma.sync gates GEMM ----------------
// Block 128m x 128n, BK=32, 8 warps (warp tile 64x32).
// Smem tile rows padded to 40 bf16 (80B) for conflict-free ldmatrix.
// Layout per buffer (bytes): [Ahi 10240][Alo 10240][Bhi 10240][Blo 10240]
#define TROW 40
#define SPLIT_BYTES 10240            // 128 * 40 * 2
#define BUF_BYTES   40960            // 4 splits
#define GEMM_SMEM   (2 * BUF_BYTES)  // 80KB

__global__ __launch_bounds__(256)
void gates_mma_kernel(const float* __restrict__ bias) {
    extern __shared__ char smem[];
    uint32_t sbase = smem_u32(smem);

    int t = threadIdx.x, l = t & 31, wid = t >> 5;
    int bn = blockIdx.x, bm = blockIdx.y;
    int wm = (wid & 1) * 64, wn = (wid >> 1) * 32;

    // ldmatrix lane offsets (bytes within a split)
    uint32_t aOff = ((wm + (l & 7) + ((l >> 3) & 1) * 8) * TROW + ((l >> 4) * 8)) * 2;
    uint32_t bOff = 2 * SPLIT_BYTES +
                    ((wn + (l & 7) + ((l >> 4) * 8)) * TROW + (((l >> 3) & 1) * 8)) * 2;

    // staging: 512 16B-units per tensor; thread handles units t and t+256
    int u0 = t, u1 = t + 256;
    int r0 = u0 >> 2, q0 = u0 & 3;
    int r1 = u1 >> 2, q1 = u1 & 3;

    const __nv_bfloat16* Ah = g_Ahi + (size_t)(bm * 128) * DIN;
    const __nv_bfloat16* Al = g_Alo + (size_t)(bm * 128) * DIN;
    const __nv_bfloat16* Bh = g_Bhi + (size_t)(bn * 128) * DIN;
    const __nv_bfloat16* Bl = g_Blo + (size_t)(bn * 128) * DIN;

    float acc[4][4][4];
#pragma unroll
    for (int i = 0; i < 4; i++)
#pragma unroll
        for (int j = 0; j < 4; j++)
#pragma unroll
            for (int k = 0; k < 4; k++) acc[i][j][k] = 0.f;

    uint4 rah[2], ral[2], rbh[2], rbl[2];

#define LDG_CHUNK(kc) {                                                        \
    int k0 = (kc) * 32;                                                        \
    rah[0] = *(const uint4*)(Ah + (size_t)r0 * DIN + k0 + q0 * 8);             \
    rah[1] = *(const uint4*)(Ah + (size_t)r1 * DIN + k0 + q1 * 8);             \
    ral[0] = *(const uint4*)(Al + (size_t)r0 * DIN + k0 + q0 * 8);             \
    ral[1] = *(const uint4*)(Al + (size_t)r1 * DIN + k0 + q1 * 8);             \
    rbh[0] = *(const uint4*)(Bh + (size_t)r0 * DIN + k0 + q0 * 8);             \
    rbh[1] = *(const uint4*)(Bh + (size_t)r1 * DIN + k0 + q1 * 8);             \
    rbl[0] = *(const uint4*)(Bl + (size_t)r0 * DIN + k0 + q0 * 8);             \
    rbl[1] = *(const uint4*)(Bl + (size_t)r1 * DIN + k0 + q1 * 8); }

#define STS_CHUNK(buf) {                                                       \
    char* sb = smem + (buf) * BUF_BYTES;                                       \
    *(uint4*)(sb + r0 * 80 + q0 * 16)                    = rah[0];             \
    *(uint4*)(sb + r1 * 80 + q1 * 16)                    = rah[1];             \
    *(uint4*)(sb + SPLIT_BYTES + r0 * 80 + q0 * 16)      = ral[0];             \
    *(uint4*)(sb + SPLIT_BYTES + r1 * 80 + q1 * 16)      = ral[1];             \
    *(uint4*)(sb + 2 * SPLIT_BYTES + r0 * 80 + q0 * 16)  = rbh[0];             \
    *(uint4*)(sb + 2 * SPLIT_BYTES + r1 * 80 + q1 * 16)  = rbh[1];             \
    *(uint4*)(sb + 3 * SPLIT_BYTES + r0 * 80 + q0 * 16)  = rbl[0];             \
    *(uint4*)(sb + 3 * SPLIT_BYTES + r1 * 80 + q1 * 16)  = rbl[1]; }

    LDG_CHUNK(0);
    STS_CHUNK(0);
    __syncthreads();

    for (int c = 0; c < 16; c++) {
        int buf = c & 1;
        if (c < 15) LDG_CHUNK(c + 1);

        uint32_t abase = sbase + buf * BUF_BYTES + aOff;
        uint32_t bbase = sbase + buf * BUF_BYTES + bOff;
#pragma unroll
        for (int kk = 0; kk < 2; kk++) {
            uint32_t kb = kk * 32;  // 16 bf16 = 32 bytes
            uint32_t fah[4][4], fbh[2][4];
#pragma unroll
            for (int mi = 0; mi < 4; mi++)
                ldsm4(fah[mi], abase + mi * 1280 + kb);
#pragma unroll
            for (int j2 = 0; j2 < 2; j2++)
                ldsm4(fbh[j2], bbase + j2 * 1280 + kb);
#pragma unroll
            for (int mi = 0; mi < 4; mi++)
#pragma unroll
                for (int nj = 0; nj < 4; nj++)
                    mma16816(acc[mi][nj], fah[mi],
                             fbh[nj >> 1][(nj & 1) * 2], fbh[nj >> 1][(nj & 1) * 2 + 1]);
            // Ahi x Blo
            uint32_t fbl[2][4];
#pragma unroll
            for (int j2 = 0; j2 < 2; j2++)
                ldsm4(fbl[j2], bbase + SPLIT_BYTES + j2 * 1280 + kb);
#pragma unroll
            for (int mi = 0; mi < 4; mi++)
#pragma unroll
                for (int nj = 0; nj < 4; nj++)
                    mma16816(acc[mi][nj], fah[mi],
                             fbl[nj >> 1][(nj & 1) * 2], fbl[nj >> 1][(nj & 1) * 2 + 1]);
            // Alo x Bhi
            uint32_t fal[4][4];
#pragma unroll
            for (int mi = 0; mi < 4; mi++)
                ldsm4(fal[mi], abase + SPLIT_BYTES + mi * 1280 + kb);
#pragma unroll
            for (int mi = 0; mi < 4; mi++)
#pragma unroll
                for (int nj = 0; nj < 4; nj++)
                    mma16816(acc[mi][nj], fal[mi],
                             fbh[nj >> 1][(nj & 1) * 2], fbh[nj >> 1][(nj & 1) * 2 + 1]);
        }

        if (c < 15) {
            STS_CHUNK(buf ^ 1);
            __syncthreads();
        }
    }

    // epilogue: c0,c1 -> (row, col..col+1); c2,c3 -> (row+8, ...)
#pragma unroll
    for (int mi = 0; mi < 4; mi++) {
        int row = bm * 128 + wm + mi * 16 + (l >> 2);
#pragma unroll
        for (int nj = 0; nj < 4; nj++) {
            int col = bn * 128 + wn + nj * 8 + 2 * (l & 3);
            float2 bv = *(const float2*)&bias[col];
            float2 v0 = make_float2(acc[mi][nj][0] + bv.x, acc[mi][nj][1] + bv.y);
            float2 v1 = make_float2(acc[mi][nj][2] + bv.x, acc[mi][nj][3] + bv.y);
            *(float2*)&g_gates[(size_t)row * G3 + col]       = v0;
            *(float2*)&g_gates[(size_t)(row + 8) * G3 + col] = v1;
        }
    }
}

// ---------------- per-bx grid barrier (32 blocks each) ----------------
__device__ __forceinline__ void grid_barrier_bx(int bx) {
    __threadfence();
    __syncthreads();
    if (threadIdx.x == 0) {
        unsigned gen = g_gen4[bx][0];
        if (atomicAdd(&g_cnt4[bx][0], 1u) == 31u) {
            g_cnt4[bx][0] = 0;
            __threadfence();
            g_gen4[bx][0] = gen + 1;
        } else {
            while (g_gen4[bx][0] == gen) { __nanosleep(32); }
        }
    }
    __syncthreads();
    __threadfence();
}

// ---------------- persistent scan kernel (round-5, unchanged) ----------------
#define K2STEP(i, hA2, hB2) {                    \
    float2 w0 = wp[(i)*48 + 0];                  \
    float2 w1 = wp[(i)*48 + 1];                  \
    float2 w2 = wp[(i)*48 + 2];                  \
    acc00 = ffma2(hA2, w0, acc00);               \
    acc01 = ffma2(hA2, w1, acc01);               \
    acc02 = ffma2(hA2, w2, acc02);               \
    acc10 = ffma2(hB2, w0, acc10);               \
    acc11 = ffma2(hB2, w1, acc11);               \
    acc12 = ffma2(hB2, w2, acc12); }

#define LOAD_CHUNK(P, c) {                                   \
    const float* pa = hApt + (c) * 16;                       \
    const float* pb = hBpt + (c) * 16;                       \
    P##a0 = *(const float4*)(pa);                            \
    P##a1 = *(const float4*)(pa + 4);                        \
    P##a2 = *(const float4*)(pa + 8);                        \
    P##a3 = *(const float4*)(pa + 12);                       \
    P##b0 = *(const float4*)(pb);                            \
    P##b1 = *(const float4*)(pb + 4);                        \
    P##b2 = *(const float4*)(pb + 8);                        \
    P##b3 = *(const float4*)(pb + 12); }

#define COMPUTE_CHUNK(P) {                                                     \
    K2STEP(0, make_float2(P##a0.x, P##a0.y), make_float2(P##b0.x, P##b0.y));   \
    K2STEP(1, make_float2(P##a0.z, P##a0.w), make_float2(P##b0.z, P##b0.w));   \
    K2STEP(2, make_float2(P##a1.x, P##a1.y), make_float2(P##b1.x, P##b1.y));   \
    K2STEP(3, make_float2(P##a1.z, P##a1.w), make_float2(P##b1.z, P##b1.w));   \
    K2STEP(4, make_float2(P##a2.x, P##a2.y), make_float2(P##b2.x, P##b2.y));   \
    K2STEP(5, make_float2(P##a2.z, P##a2.w), make_float2(P##b2.z, P##b2.w));   \
    K2STEP(6, make_float2(P##a3.x, P##a3.y), make_float2(P##b3.x, P##b3.y));   \
    K2STEP(7, make_float2(P##a3.z, P##a3.w), make_float2(P##b3.z, P##b3.w));   \
    wp += 8 * 48; }

__global__ __launch_bounds__(256)
void scan_kernel(const float* __restrict__ carry,
                 const void*  __restrict__ resets,
                 float* __restrict__ outputs,
                 float* __restrict__ carry_out) {
    extern __shared__ float sm[];   // W slice: 24576 floats (96KB)

    int t   = threadIdx.x;
    int bid = blockIdx.x;
    int bx  = bid & 3, by = bid >> 2;
    int b0  = bx * 32, hh0 = by * 16;
    int tx  = t & 15,  ty = t >> 4;
    int mode = g_reset_mode;
    int hh  = hh0 + tx;
    int bA  = b0 + ty * 2, bB = bA + 1;

    {
        const float* Wslice = (const float*)g_Whr[by];
        for (int i = t * 4; i < 24576; i += 256 * 4)
            *(float4*)(sm + i) = *(const float4*)(Wslice + i);
    }
    __syncthreads();
    const float2* Wk = (const float2*)sm + tx * 3;

    const unsigned char* rbytes = (const unsigned char*)resets;
    const int*           rints  = (const int*)resets;

    float pzA, prA, pnA, pzB, prB, pnB, prmA, prmB;
    {
        size_t gA = (size_t)bA * G3;
        size_t gB = (size_t)bB * G3;
        pzA = g_gates[gA + hh]; prA = g_gates[gA + HDIM + hh]; pnA = g_gates[gA + 2*HDIM + hh];
        pzB = g_gates[gB + hh]; prB = g_gates[gB + HDIM + hh]; pnB = g_gates[gB + 2*HDIM + hh];
        bool rsA = (mode == 0) ? (rints[bA] != 0) : (rbytes[bA] != 0);
        bool rsB = (mode == 0) ? (rints[bB] != 0) : (rbytes[bB] != 0);
        prmA = rsA ? 0.f : 1.f;
        prmB = rsB ? 0.f : 1.f;
    }
    float hpA = carry[(size_t)bA * HDIM + hh];
    float hpB = carry[(size_t)bB * HDIM + hh];

    for (int s = 0; s < SEQ; s++) {
        const float* h_in = (s == 0) ? carry
                                     : outputs + (size_t)(s - 1) * BATCH * HDIM;
        const float* hApt = h_in + (size_t)bA * HDIM;
        const float* hBpt = h_in + (size_t)bB * HDIM;

        float zA = pzA, rA = prA, nA = pnA;
        float zB = pzB, rB = prB, nB = pnB;
        float rmA = prmA, rmB = prmB;

        float2 acc00 = make_float2(0.f, 0.f), acc01 = acc00, acc02 = acc00;
        float2 acc10 = acc00, acc11 = acc00, acc12 = acc00;

        const float2* wp = Wk;
        float4 Xa0, Xa1, Xa2, Xa3, Xb0, Xb1, Xb2, Xb3;
        float4 Ya0, Ya1, Ya2, Ya3, Yb0, Yb1, Yb2, Yb3;

        LOAD_CHUNK(X, 0);
        for (int c = 0; c < 30; c += 2) {
            LOAD_CHUNK(Y, c + 1);
            COMPUTE_CHUNK(X);
            LOAD_CHUNK(X, c + 2);
            COMPUTE_CHUNK(Y);
        }
        LOAD_CHUNK(Y, 31);
        COMPUTE_CHUNK(X);
        COMPUTE_CHUNK(Y);

        {
            float zh = rmA * (acc00.x + acc00.y);
            float rh = rmA * (acc01.x + acc01.y);
            float nh = rmA * (acc02.x + acc02.y);
            float z = 1.f / (1.f + __expf(-(zA + zh)));
            float r = 1.f / (1.f + __expf(-(rA + rh)));
            float n = tanhf(nA + r * nh);
            float hnew = (1.f - z) * n + z * (hpA * rmA);
            outputs[((size_t)s * BATCH + bA) * HDIM + hh] = hnew;
            if (carry_out && s == SEQ - 1) carry_out[(size_t)bA * HDIM + hh] = hnew;
            hpA = hnew;
        }
        {
            float zh = rmB * (acc10.x + acc10.y);
            float rh = rmB * (acc11.x + acc11.y);
            float nh = rmB * (acc12.x + acc12.y);
            float z = 1.f / (1.f + __expf(-(zB + zh)));
            float r = 1.f / (1.f + __expf(-(rB + rh)));
            float n = tanhf(nB + r * nh);
            float hnew = (1.f - z) * n + z * (hpB * rmB);
            outputs[((size_t)s * BATCH + bB) * HDIM + hh] = hnew;
            if (carry_out && s == SEQ - 1) carry_out[(size_t)bB * HDIM + hh] = hnew;
            hpB = hnew;
        }

        {
            int sn = (s + 1 < SEQ) ? s + 1 : s;
            size_t gA = ((size_t)sn * BATCH + bA) * G3;
            size_t gB = ((size_t)sn * BATCH + bB) * G3;
            pzA = g_gates[gA + hh]; prA = g_gates[gA + HDIM + hh]; pnA = g_gates[gA + 2*HDIM + hh];
            pzB = g_gates[gB + hh]; prB = g_gates[gB + HDIM + hh]; pnB = g_gates[gB + 2*HDIM + hh];
            int ri = sn * BATCH;
            bool rsA = (mode == 0) ? (rints[ri + bA] != 0) : (rbytes[ri + bA] != 0);
            bool rsB = (mode == 0) ? (rints[ri + bB] != 0) : (rbytes[ri + bB] != 0);
            prmA = rsA ? 0.f : 1.f;
            prmB = rsB ? 0.f : 1.f;
        }

        if (s < SEQ - 1) grid_barrier_bx(bx);
    }
}

// ---------------- launcher ----------------
extern "C" void kernel_launch(void* const* d_in, const int* in_sizes, int n_in,
                              void* d_out, int out_size) {
    const float* carry = (const float*)d_in[0];
    const float* ins   = (const float*)d_in[1];
    const void*  rsts  = d_in[2];
    const float* W_in  = (const float*)d_in[3];
    const float* b_in  = (const float*)d_in[4];
    const float* W_h   = (const float*)d_in[5];

    float* out = (float*)d_out;
    float* carry_out;
    float* outputs;
    if (out_size == (int)((size_t)SEQ * BATCH * HDIM)) {
        carry_out = nullptr;
        outputs   = out;
    } else {
        carry_out = out;
        outputs   = out + (size_t)BATCH * HDIM;
    }

    const int SMEM_SCAN = 24576 * sizeof(float);
    cudaFuncSetAttribute(scan_kernel,
                         cudaFuncAttributeMaxDynamicSharedMemorySize, SMEM_SCAN);
    cudaFuncSetAttribute(gates_mma_kernel,
                         cudaFuncAttributeMaxDynamicSharedMemorySize, GEMM_SMEM);

    init_kernel<<<1, 32>>>((const unsigned int*)rsts);
    rearrange_wh_kernel<<<(32 * 256 * 48 * 2 + 255) / 256, 256>>>(W_h);
    prep_a_kernel<<<(int)(((size_t)MROWS * DIN / 4 + 255) / 256), 256>>>(ins);
    prep_w_kernel<<<(G3 * DIN + 255) / 256, 256>>>(W_in);
    gates_mma_kernel<<<dim3(G3 / 128, MROWS / 128), 256, GEMM_SMEM>>>(b_in);
    scan_kernel<<<SCAN_BLOCKS, 256, SMEM_SCAN>>>(carry, rsts, outputs, carry_out);
}

// round 9
// speedup vs baseline: 2.2278x; 1.8026x over previous
#include <cuda_runtime.h>
#include <cuda_bf16.h>
#include <math.h>
#include <stdint.h>

#define SEQ   512
#define BATCH 128
#define DIN   512
#define HDIM  512
#define G3    1536
#define MROWS (SEQ * BATCH)        // 65536

// ---------------- scratch (device globals) ----------------
__device__ float g_gates[(size_t)SEQ * BATCH * G3];          // ~402MB
__device__ __nv_bfloat16 g_Ahi[(size_t)MROWS * DIN];
__device__ __nv_bfloat16 g_Alo[(size_t)MROWS * DIN];
__device__ __nv_bfloat16 g_Bhi[(size_t)G3 * DIN];            // W_in^T hi [n][k]
__device__ __nv_bfloat16 g_Blo[(size_t)G3 * DIN];            // W_in^T lo [n][k]
__device__ __nv_bfloat16 g_Wh16[(size_t)2 * 32 * 48 * DIN];  // W_h split [split][by][c][k]
__device__ __nv_bfloat16 g_h16[2][2][(size_t)BATCH * HDIM];  // [parity][split][b*512+hh]
__device__ int      g_reset_mode;
__device__ unsigned g_done[SEQ * 4];                         // per-(step,bx) counters

// ---------------- mma.sync helpers ----------------
__device__ __forceinline__ uint32_t smem_u32(const void* p) {
    return (uint32_t)__cvta_generic_to_shared(p);
}
__device__ __forceinline__ void ldsm4(uint32_t* r, uint32_t addr) {
    asm volatile("ldmatrix.sync.aligned.m8n8.x4.shared.b16 {%0,%1,%2,%3}, [%4];"
                 : "=r"(r[0]), "=r"(r[1]), "=r"(r[2]), "=r"(r[3]) : "r"(addr));
}
__device__ __forceinline__ void mma16816(float* c, const uint32_t* a,
                                         uint32_t b0, uint32_t b1) {
    asm volatile(
        "mma.sync.aligned.m16n8k16.row.col.f32.bf16.bf16.f32 "
        "{%0,%1,%2,%3}, {%4,%5,%6,%7}, {%8,%9}, {%0,%1,%2,%3};"
        : "+f"(c[0]), "+f"(c[1]), "+f"(c[2]), "+f"(c[3])
        : "r"(a[0]), "r"(a[1]), "r"(a[2]), "r"(a[3]), "r"(b0), "r"(b1));
}
__device__ __forceinline__ unsigned ld_acq(const unsigned* p) {
    unsigned v;
    asm volatile("ld.acquire.gpu.global.u32 %0, [%1];" : "=r"(v) : "l"(p) : "memory");
    return v;
}
__device__ __forceinline__ void red_rel(unsigned* p) {
    asm volatile("red.release.gpu.global.add.u32 [%0], 1;" :: "l"(p) : "memory");
}

// ---------------- init + reset dtype sniffing ----------------
__global__ void init_kernel(const unsigned int* __restrict__ r) {
    int t = blockIdx.x * 256 + threadIdx.x;
    for (int i = t; i < SEQ * 4; i += 512) g_done[i] = 0u;
    if (t == 0) {
        bool word_mode = true;
        for (int i = 0; i < 64; i++) {
            unsigned v = r[i];
            if (!(v == 0u || v == 1u || v == 0x3F800000u)) { word_mode = false; break; }
        }
        g_reset_mode = word_mode ? 0 : 2;
    }
}

// ---------------- prep kernels ----------------
__global__ void prep_a_kernel(const float* __restrict__ ins) {
    size_t base = ((size_t)blockIdx.x * 256 + threadIdx.x) * 4;
    if (base < (size_t)MROWS * DIN) {
        float4 v = *(const float4*)(ins + base);
        float x[4] = {v.x, v.y, v.z, v.w};
#pragma unroll
        for (int i = 0; i < 4; i++) {
            __nv_bfloat16 h = __float2bfloat16(x[i]);
            g_Ahi[base + i] = h;
            g_Alo[base + i] = __float2bfloat16(x[i] - __bfloat162float(h));
        }
    }
}
__global__ void prep_w_kernel(const float* __restrict__ W) {
    int idx = blockIdx.x * 256 + threadIdx.x;
    if (idx < G3 * DIN) {
        int n = idx >> 9, k = idx & 511;
        float x = W[(size_t)k * G3 + n];
        __nv_bfloat16 h = __float2bfloat16(x);
        g_Bhi[idx] = h;
        g_Blo[idx] = __float2bfloat16(x - __bfloat162float(h));
    }
}
// W_h split: [split][by][c(0..47)][k];  c: 0-15 z, 16-31 r, 32-47 n; hh = by*16 + (c&15)
__global__ void prep_wh_kernel(const float* __restrict__ Wh) {
    int idx = blockIdx.x * 256 + threadIdx.x;   // over 32*48*512
    if (idx < 32 * 48 * DIN) {
        int k  = idx & 511;
        int c  = (idx >> 9) % 48;
        int by = idx / (48 * DIN);
        int j  = c >> 4;
        int hh = by * 16 + (c & 15);
        float x = Wh[(size_t)k * G3 + j * HDIM + hh];
        __nv_bfloat16 h = __float2bfloat16(x);
        size_t o = ((size_t)by * 48 + c) * DIN + k;
        g_Wh16[o] = h;
        g_Wh16[(size_t)32 * 48 * DIN + o] = __float2bfloat16(x - __bfloat162float(h));
    }
}
__global__ void prep_h0_kernel(const float* __restrict__ carry) {
    int idx = blockIdx.x * 256 + threadIdx.x;
    if (idx < BATCH * HDIM) {
        float x = carry[idx];
        __nv_bfloat16 h = __float2bfloat16(x);
        g_h16[0][0][idx] = h;
        g_h16[0][1][idx] = __float2bfloat16(x - __bfloat162float(h));
    }
}

// ---------------- mma.sync gates GEMM (round-8, unchanged) ----------------
#define TROW 40
#define SPLIT_BYTES 10240
#define BUF_BYTES   40960
#define GEMM_SMEM   (2 * BUF_BYTES)

__global__ __launch_bounds__(256)
void gates_mma_kernel(const float* __restrict__ bias) {
    extern __shared__ char smem[];
    uint32_t sbase = smem_u32(smem);

    int t = threadIdx.x, l = t & 31, wid = t >> 5;
    int bn = blockIdx.x, bm = blockIdx.y;
    int wm = (wid & 1) * 64, wn = (wid >> 1) * 32;

    uint32_t aOff = ((wm + (l & 7) + ((l >> 3) & 1) * 8) * TROW + ((l >> 4) * 8)) * 2;
    uint32_t bOff = 2 * SPLIT_BYTES +
                    ((wn + (l & 7) + ((l >> 4) * 8)) * TROW + (((l >> 3) & 1) * 8)) * 2;

    int u0 = t, u1 = t + 256;
    int r0 = u0 >> 2, q0 = u0 & 3;
    int r1 = u1 >> 2, q1 = u1 & 3;

    const __nv_bfloat16* Ah = g_Ahi + (size_t)(bm * 128) * DIN;
    const __nv_bfloat16* Al = g_Alo + (size_t)(bm * 128) * DIN;
    const __nv_bfloat16* Bh = g_Bhi + (size_t)(bn * 128) * DIN;
    const __nv_bfloat16* Bl = g_Blo + (size_t)(bn * 128) * DIN;

    float acc[4][4][4];
#pragma unroll
    for (int i = 0; i < 4; i++)
#pragma unroll
        for (int j = 0; j < 4; j++)
#pragma unroll
            for (int k = 0; k < 4; k++) acc[i][j][k] = 0.f;

    uint4 rah[2], ral[2], rbh[2], rbl[2];

#define LDG_CHUNK(kc) {                                                        \
    int k0 = (kc) * 32;                                                        \
    rah[0] = *(const uint4*)(Ah + (size_t)r0 * DIN + k0 + q0 * 8);             \
    rah[1] = *(const uint4*)(Ah + (size_t)r1 * DIN + k0 + q1 * 8);             \
    ral[0] = *(const uint4*)(Al + (size_t)r0 * DIN + k0 + q0 * 8);             \
    ral[1] = *(const uint4*)(Al + (size_t)r1 * DIN + k0 + q1 * 8);             \
    rbh[0] = *(const uint4*)(Bh + (size_t)r0 * DIN + k0 + q0 * 8);             \
    rbh[1] = *(const uint4*)(Bh + (size_t)r1 * DIN + k0 + q1 * 8);             \
    rbl[0] = *(const uint4*)(Bl + (size_t)r0 * DIN + k0 + q0 * 8);             \
    rbl[1] = *(const uint4*)(Bl + (size_t)r1 * DIN + k0 + q1 * 8); }

#define STS_CHUNK(buf) {                                                       \
    char* sb = smem + (buf) * BUF_BYTES;                                       \
    *(uint4*)(sb + r0 * 80 + q0 * 16)                    = rah[0];             \
    *(uint4*)(sb + r1 * 80 + q1 * 16)                    = rah[1];             \
    *(uint4*)(sb + SPLIT_BYTES + r0 * 80 + q0 * 16)      = ral[0];             \
    *(uint4*)(sb + SPLIT_BYTES + r1 * 80 + q1 * 16)      = ral[1];             \
    *(uint4*)(sb + 2 * SPLIT_BYTES + r0 * 80 + q0 * 16)  = rbh[0];             \
    *(uint4*)(sb + 2 * SPLIT_BYTES + r1 * 80 + q1 * 16)  = rbh[1];             \
    *(uint4*)(sb + 3 * SPLIT_BYTES + r0 * 80 + q0 * 16)  = rbl[0];             \
    *(uint4*)(sb + 3 * SPLIT_BYTES + r1 * 80 + q1 * 16)  = rbl[1]; }

    LDG_CHUNK(0);
    STS_CHUNK(0);
    __syncthreads();

    for (int c = 0; c < 16; c++) {
        int buf = c & 1;
        if (c < 15) LDG_CHUNK(c + 1);

        uint32_t abase = sbase + buf * BUF_BYTES + aOff;
        uint32_t bbase = sbase + buf * BUF_BYTES + bOff;
#pragma unroll
        for (int kk = 0; kk < 2; kk++) {
            uint32_t kb = kk * 32;
            uint32_t fah[4][4], fbh[2][4];
#pragma unroll
            for (int mi = 0; mi < 4; mi++)
                ldsm4(fah[mi], abase + mi * 1280 + kb);
#pragma unroll
            for (int j2 = 0; j2 < 2; j2++)
                ldsm4(fbh[j2], bbase + j2 * 1280 + kb);
#pragma unroll
            for (int mi = 0; mi < 4; mi++)
#pragma unroll
                for (int nj = 0; nj < 4; nj++)
                    mma16816(acc[mi][nj], fah[mi],
                             fbh[nj >> 1][(nj & 1) * 2], fbh[nj >> 1][(nj & 1) * 2 + 1]);
            uint32_t fbl[2][4];
#pragma unroll
            for (int j2 = 0; j2 < 2; j2++)
                ldsm4(fbl[j2], bbase + SPLIT_BYTES + j2 * 1280 + kb);
#pragma unroll
            for (int mi = 0; mi < 4; mi++)
#pragma unroll
                for (int nj = 0; nj < 4; nj++)
                    mma16816(acc[mi][nj], fah[mi],
                             fbl[nj >> 1][(nj & 1) * 2], fbl[nj >> 1][(nj & 1) * 2 + 1]);
            uint32_t fal[4][4];
#pragma unroll
            for (int mi = 0; mi < 4; mi++)
                ldsm4(fal[mi], abase + SPLIT_BYTES + mi * 1280 + kb);
#pragma unroll
            for (int mi = 0; mi < 4; mi++)
#pragma unroll
                for (int nj = 0; nj < 4; nj++)
                    mma16816(acc[mi][nj], fal[mi],
                             fbh[nj >> 1][(nj & 1) * 2], fbh[nj >> 1][(nj & 1) * 2 + 1]);
        }

        if (c < 15) {
            STS_CHUNK(buf ^ 1);
            __syncthreads();
        }
    }

#pragma unroll
    for (int mi = 0; mi < 4; mi++) {
        int row = bm * 128 + wm + mi * 16 + (l >> 2);
#pragma unroll
        for (int nj = 0; nj < 4; nj++) {
            int col = bn * 128 + wn + nj * 8 + 2 * (l & 3);
            float2 bv = *(const float2*)&bias[col];
            float2 v0 = make_float2(acc[mi][nj][0] + bv.x, acc[mi][nj][1] + bv.y);
            float2 v1 = make_float2(acc[mi][nj][2] + bv.x, acc[mi][nj][3] + bv.y);
            *(float2*)&g_gates[(size_t)row * G3 + col]       = v0;
            *(float2*)&g_gates[(size_t)(row + 8) * G3 + col] = v1;
        }
    }
}

// ---------------- mma.sync persistent scan ----------------
// 128 blocks (bx=bid&3: 32 batches; by=bid>>2: 16 hh). Per step:
//   C[32 b][48 c] = Hs[32 b][512 k] * Ws[48 c][512 k]^T  (bf16 hi/lo split, 3 products)
// Smem: A (H) 2 splits x 32 x 1040B; B (W, persistent) 2 x 48 x 1040B; red 8x768 fp32.
#define HROWB   1040
#define A_HI    0
#define A_LO    33280
#define B_HI    66560
#define B_LO    116480
#define RED_OFF 166400
#define SCAN_SMEM (RED_OFF + 8 * 768 * 4)   // 190976

__global__ __launch_bounds__(256)
void scan_mma_kernel(const float* __restrict__ carry,
                     const void*  __restrict__ resets,
                     float* __restrict__ outputs,
                     float* __restrict__ carry_out) {
    extern __shared__ char smem[];
    uint32_t sbase = smem_u32(smem);

    int t = threadIdx.x, l = t & 31, wid = t >> 5;
    int kw = wid & 3, mw = wid >> 2;
    int bid = blockIdx.x;
    int bx = bid & 3, by = bid >> 2;
    int b0 = bx * 32;
    int hh0g = by * 16;
    int mode = g_reset_mode;

    const unsigned char* rbytes = (const unsigned char*)resets;
    const int*           rints  = (const int*)resets;

    // ---- one-time: W slices into smem (48 rows x 1024B per split) ----
    {
        const char* wg = (const char*)g_Wh16;
#pragma unroll
        for (int sp = 0; sp < 2; sp++) {
            size_t gbase = ((size_t)sp * 32 + by) * 48 * DIN * 2;
#pragma unroll
            for (int i = 0; i < 12; i++) {
                int u = t + i * 256;          // 16B units, 64 per row
                int row = u >> 6, off = (u & 63) * 16;
                *(uint4*)(smem + B_HI + sp * 49920 + row * HROWB + off) =
                    *(const uint4*)(wg + gbase + (size_t)row * 1024 + off);
            }
        }
    }

    // ldmatrix lane offsets
    uint32_t aoff = sbase + A_HI +
        (uint32_t)((mw * 16 + (l & 7) + ((l >> 3) & 1) * 8) * HROWB + ((l >> 4) * 8) * 2);
    uint32_t boff = sbase + B_HI +
        (uint32_t)(((l & 7) + ((l >> 4) * 8)) * HROWB + (((l >> 3) & 1) * 8) * 2);

    // staging identity: row srow (0..31), 128B chunk
    int srow = t >> 3, scoff = (t & 7) * 128;

    // epilogue identity: batch eb (0..31), hh pair ehh0
    int eb = t >> 3, ehh0 = (t & 7) * 2;
    int gb = b0 + eb;
    int ghh = hh0g + ehh0;
    int emw = eb >> 4, erow8 = (eb >> 3) & 1, erowl = eb & 7;

    float hp0 = carry[(size_t)gb * HDIM + ghh];
    float hp1 = carry[(size_t)gb * HDIM + ghh + 1];

    float* redf = (float*)(smem + RED_OFF);
    __syncthreads();   // W staged

    for (int s = 0; s < SEQ; s++) {
        int par = s & 1;

        // prefetch gates + epilogue reset mask (DRAM latency hidden under poll/stage/mma)
        size_t grow = ((size_t)s * BATCH + gb) * G3;
        float2 gz = *(const float2*)&g_gates[grow + ghh];
        float2 gr = *(const float2*)&g_gates[grow + HDIM + ghh];
        float2 gn = *(const float2*)&g_gates[grow + 2 * HDIM + ghh];
        bool ers = (mode == 0) ? (rints[s * BATCH + gb] != 0)
                               : (rbytes[s * BATCH + gb] != 0);
        float em = ers ? 0.f : 1.f;
        bool srs = (mode == 0) ? (rints[s * BATCH + b0 + srow] != 0)
                               : (rbytes[s * BATCH + b0 + srow] != 0);

        // wait for previous step's h (all 32 by-blocks of this bx)
        if (s > 0) {
            if (l == 0) {
                unsigned* cp = &g_done[(s - 1) * 4 + bx];
                while (ld_acq(cp) < 32u) { }
            }
            __syncwarp();
        }

        // ---- stage H (masked) ----
        {
            const char* ghi = (const char*)&g_h16[par][0][(size_t)(b0 + srow) * HDIM] + scoff;
            const char* glo = (const char*)&g_h16[par][1][(size_t)(b0 + srow) * HDIM] + scoff;
            char* shi = smem + A_HI + srow * HROWB + scoff;
            char* slo = smem + A_LO + srow * HROWB + scoff;
            if (srs) {
                uint4 z = make_uint4(0, 0, 0, 0);
#pragma unroll
                for (int i = 0; i < 8; i++) {
                    *(uint4*)(shi + i * 16) = z;
                    *(uint4*)(slo + i * 16) = z;
                }
            } else {
#pragma unroll
                for (int i = 0; i < 8; i++) {
                    *(uint4*)(shi + i * 16) = *(const uint4*)(ghi + i * 16);
                    *(uint4*)(slo + i * 16) = *(const uint4*)(glo + i * 16);
                }
            }
        }
        __syncthreads();

        // ---- mma over this warp's K range ----
        float acc[6][4];
#pragma unroll
        for (int i = 0; i < 6; i++)
#pragma unroll
            for (int j = 0; j < 4; j++) acc[i][j] = 0.f;

#pragma unroll
        for (int kt = 0; kt < 8; kt++) {
            uint32_t kb = (uint32_t)(kw * 256 + kt * 32);
            uint32_t fah[4], fal[4], fbh[3][4], fbl[3][4];
            ldsm4(fah, aoff + kb);
            ldsm4(fal, aoff + A_LO + kb);
#pragma unroll
            for (int j2 = 0; j2 < 3; j2++) {
                ldsm4(fbh[j2], boff + j2 * 16640 + kb);
                ldsm4(fbl[j2], boff + 49920 + j2 * 16640 + kb);
            }
#pragma unroll
            for (int j2 = 0; j2 < 3; j2++)
#pragma unroll
                for (int sub = 0; sub < 2; sub++) {
                    int nt = j2 * 2 + sub;
                    mma16816(acc[nt], fah, fbh[j2][sub * 2], fbh[j2][sub * 2 + 1]);
                    mma16816(acc[nt], fah, fbl[j2][sub * 2], fbl[j2][sub * 2 + 1]);
                    mma16816(acc[nt], fal, fbh[j2][sub * 2], fbh[j2][sub * 2 + 1]);
                }
        }

        // ---- cross-warp reduction via smem ----
        {
            float* rw = redf + wid * 768;
#pragma unroll
            for (int nt = 0; nt < 6; nt++)
#pragma unroll
                for (int c = 0; c < 4; c++)
                    rw[(nt * 4 + c) * 32 + l] = acc[nt][c];
        }
        __syncthreads();

        // ---- epilogue: 2 h values per thread ----
        float hn[2];
#pragma unroll
        for (int q = 0; q < 2; q++) {
            int hh = ehh0 + q;
            int nt01 = hh >> 3, hl = hh & 7;
            int lane = erowl * 4 + (hl >> 1);
            int creg = erow8 * 2 + (hh & 1);
            float sz = 0.f, sr = 0.f, sn = 0.f;
#pragma unroll
            for (int kwp = 0; kwp < 4; kwp++) {
                const float* rb = redf + (emw * 4 + kwp) * 768;
                sz += rb[((0 * 2 + nt01) * 4 + creg) * 32 + lane];
                sr += rb[((1 * 2 + nt01) * 4 + creg) * 32 + lane];
                sn += rb[((2 * 2 + nt01) * 4 + creg) * 32 + lane];
            }
            float giz = q ? gz.y : gz.x;
            float gir = q ? gr.y : gr.x;
            float gin = q ? gn.y : gn.x;
            float hp  = q ? hp1 : hp0;
            float z = 1.f / (1.f + __expf(-(giz + sz)));
            float r = 1.f / (1.f + __expf(-(gir + sr)));
            float n = tanhf(gin + r * sn);
            hn[q] = (1.f - z) * n + z * (hp * em);
        }
        hp0 = hn[0]; hp1 = hn[1];

        // stores: fp32 outputs + bf16 hi/lo for next step
        *(float2*)&outputs[((size_t)s * BATCH + gb) * HDIM + ghh] = make_float2(hn[0], hn[1]);
        {
            __nv_bfloat16 h0 = __float2bfloat16(hn[0]);
            __nv_bfloat16 h1 = __float2bfloat16(hn[1]);
            __nv_bfloat16 l0 = __float2bfloat16(hn[0] - __bfloat162float(h0));
            __nv_bfloat16 l1 = __float2bfloat16(hn[1] - __bfloat162float(h1));
            *(__nv_bfloat162*)&g_h16[par ^ 1][0][(size_t)gb * HDIM + ghh] =
                make_bfloat162(h0, h1);
            *(__nv_bfloat162*)&g_h16[par ^ 1][1][(size_t)gb * HDIM + ghh] =
                make_bfloat162(l0, l1);
        }
        if (carry_out && s == SEQ - 1)
            *(float2*)&carry_out[(size_t)gb * HDIM + ghh] = make_float2(hn[0], hn[1]);

        __syncthreads();                 // all block stores issued (program order)
        if (t == 0 && s < SEQ - 1) red_rel(&g_done[s * 4 + bx]);
    }
}

// ---------------- launcher ----------------
extern "C" void kernel_launch(void* const* d_in, const int* in_sizes, int n_in,
                              void* d_out, int out_size) {
    const float* carry = (const float*)d_in[0];
    const float* ins   = (const float*)d_in[1];
    const void*  rsts  = d_in[2];
    const float* W_in  = (const float*)d_in[3];
    const float* b_in  = (const float*)d_in[4];
    const float* W_h   = (const float*)d_in[5];

    float* out = (float*)d_out;
    float* carry_out;
    float* outputs;
    if (out_size == (int)((size_t)SEQ * BATCH * HDIM)) {
        carry_out = nullptr;
        outputs   = out;
    } else {
        carry_out = out;
        outputs   = out + (size_t)BATCH * HDIM;
    }

    cudaFuncSetAttribute(gates_mma_kernel,
                         cudaFuncAttributeMaxDynamicSharedMemorySize, GEMM_SMEM);
    cudaFuncSetAttribute(scan_mma_kernel,
                         cudaFuncAttributeMaxDynamicSharedMemorySize, SCAN_SMEM);

    init_kernel<<<2, 256>>>((const unsigned int*)rsts);
    prep_a_kernel<<<(int)(((size_t)MROWS * DIN / 4 + 255) / 256), 256>>>(ins);
    prep_w_kernel<<<(G3 * DIN + 255) / 256, 256>>>(W_in);
    prep_wh_kernel<<<(32 * 48 * DIN + 255) / 256, 256>>>(W_h);
    prep_h0_kernel<<<(BATCH * HDIM + 255) / 256, 256>>>(carry);
    gates_mma_kernel<<<dim3(G3 / 128, MROWS / 128), 256, GEMM_SMEM>>>(b_in);
    scan_mma_kernel<<<128, 256, SCAN_SMEM>>>(carry, rsts, outputs, carry_out);
}

// round 10
// speedup vs baseline: 2.3151x; 1.0392x over previous
#include <cuda_runtime.h>
#include <cuda_bf16.h>
#include <math.h>
#include <stdint.h>

#define SEQ   512
#define BATCH 128
#define DIN   512
#define HDIM  512
#define G3    1536
#define MROWS (SEQ * BATCH)        // 65536

// ---------------- scratch (device globals) ----------------
__device__ float g_gates[(size_t)SEQ * BATCH * G3];          // ~402MB
__device__ __nv_bfloat16 g_Bhi[(size_t)G3 * DIN];            // W_in^T hi [n][k]
__device__ __nv_bfloat16 g_Blo[(size_t)G3 * DIN];            // W_in^T lo [n][k]
__device__ __nv_bfloat16 g_Wh16[(size_t)2 * 32 * 48 * DIN];  // W_h split [split][by][c][k]
__device__ __nv_bfloat16 g_h16[2][2][(size_t)BATCH * HDIM];  // [parity][split][b*512+hh]
__device__ int      g_reset_mode;
__device__ unsigned g_done[SEQ * 4];                         // per-(step,bx) counters

// ---------------- mma.sync helpers ----------------
__device__ __forceinline__ uint32_t smem_u32(const void* p) {
    return (uint32_t)__cvta_generic_to_shared(p);
}
__device__ __forceinline__ void ldsm4(uint32_t* r, uint32_t addr) {
    asm volatile("ldmatrix.sync.aligned.m8n8.x4.shared.b16 {%0,%1,%2,%3}, [%4];"
                 : "=r"(r[0]), "=r"(r[1]), "=r"(r[2]), "=r"(r[3]) : "r"(addr));
}
__device__ __forceinline__ void mma16816(float* c, const uint32_t* a,
                                         uint32_t b0, uint32_t b1) {
    asm volatile(
        "mma.sync.aligned.m16n8k16.row.col.f32.bf16.bf16.f32 "
        "{%0,%1,%2,%3}, {%4,%5,%6,%7}, {%8,%9}, {%0,%1,%2,%3};"
        : "+f"(c[0]), "+f"(c[1]), "+f"(c[2]), "+f"(c[3])
        : "r"(a[0]), "r"(a[1]), "r"(a[2]), "r"(a[3]), "r"(b0), "r"(b1));
}
__device__ __forceinline__ unsigned ld_acq(const unsigned* p) {
    unsigned v;
    asm volatile("ld.acquire.gpu.global.u32 %0, [%1];" : "=r"(v) : "l"(p) : "memory");
    return v;
}
__device__ __forceinline__ void red_rel(unsigned* p) {
    asm volatile("red.release.gpu.global.add.u32 [%0], 1;" :: "l"(p) : "memory");
}
// pack two bf16 into a uint32 (low = first)
__device__ __forceinline__ uint32_t pack2(__nv_bfloat16 a, __nv_bfloat16 b) {
    __nv_bfloat162 v; v.x = a; v.y = b;
    return *(uint32_t*)&v;
}
// split one float into (hi, lo) bf16
__device__ __forceinline__ void split1(float x, __nv_bfloat16& h, __nv_bfloat16& l) {
    h = __float2bfloat16(x);
    l = __float2bfloat16(x - __bfloat162float(h));
}

// ---------------- init + reset dtype sniffing ----------------
__global__ void init_kernel(const unsigned int* __restrict__ r) {
    int t = blockIdx.x * 256 + threadIdx.x;
    for (int i = t; i < SEQ * 4; i += 512) g_done[i] = 0u;
    if (t == 0) {
        bool word_mode = true;
        for (int i = 0; i < 64; i++) {
            unsigned v = r[i];
            if (!(v == 0u || v == 1u || v == 0x3F800000u)) { word_mode = false; break; }
        }
        g_reset_mode = word_mode ? 0 : 2;
    }
}

// ---------------- prep kernels (W only; A split fused into gemm) ----------------
__global__ void prep_w_kernel(const float* __restrict__ W) {
    int idx = blockIdx.x * 256 + threadIdx.x;
    if (idx < G3 * DIN) {
        int n = idx >> 9, k = idx & 511;
        float x = W[(size_t)k * G3 + n];
        __nv_bfloat16 h, l;
        split1(x, h, l);
        g_Bhi[idx] = h;
        g_Blo[idx] = l;
    }
}
// W_h split: [split][by][c(0..47)][k];  c: 0-15 z, 16-31 r, 32-47 n; hh = by*16 + (c&15)
__global__ void prep_wh_kernel(const float* __restrict__ Wh) {
    int idx = blockIdx.x * 256 + threadIdx.x;   // over 32*48*512
    if (idx < 32 * 48 * DIN) {
        int k  = idx & 511;
        int c  = (idx >> 9) % 48;
        int by = idx / (48 * DIN);
        int j  = c >> 4;
        int hh = by * 16 + (c & 15);
        float x = Wh[(size_t)k * G3 + j * HDIM + hh];
        __nv_bfloat16 h, l;
        split1(x, h, l);
        size_t o = ((size_t)by * 48 + c) * DIN + k;
        g_Wh16[o] = h;
        g_Wh16[(size_t)32 * 48 * DIN + o] = l;
    }
}

// ---------------- mma.sync gates GEMM (fp32 A read, split fused in staging) ----------------
#define TROW 40
#define SPLIT_BYTES 10240
#define BUF_BYTES   40960
#define GEMM_SMEM   (2 * BUF_BYTES)

__global__ __launch_bounds__(256)
void gates_mma_kernel(const float* __restrict__ A,      // ins fp32 [65536][512]
                      const float* __restrict__ bias) {
    extern __shared__ char smem[];
    uint32_t sbase = smem_u32(smem);

    int t = threadIdx.x, l = t & 31, wid = t >> 5;
    int bn = blockIdx.x, bm = blockIdx.y;
    int wm = (wid & 1) * 64, wn = (wid >> 1) * 32;

    uint32_t aOff = ((wm + (l & 7) + ((l >> 3) & 1) * 8) * TROW + ((l >> 4) * 8)) * 2;
    uint32_t bOff = 2 * SPLIT_BYTES +
                    ((wn + (l & 7) + ((l >> 4) * 8)) * TROW + (((l >> 3) & 1) * 8)) * 2;

    // A staging (fp32): 128 rows x 32 k = 1024 float4 units; 4 per thread
    int rA[4], qA[4];
#pragma unroll
    for (int i = 0; i < 4; i++) { int u = t + i * 256; rA[i] = u >> 3; qA[i] = u & 7; }
    // B staging (bf16): 512 uint4 units per split; 2 per thread
    int u0 = t, u1 = t + 256;
    int r0 = u0 >> 2, q0 = u0 & 3;
    int r1 = u1 >> 2, q1 = u1 & 3;

    const float*         Af = A     + (size_t)(bm * 128) * DIN;
    const __nv_bfloat16* Bh = g_Bhi + (size_t)(bn * 128) * DIN;
    const __nv_bfloat16* Bl = g_Blo + (size_t)(bn * 128) * DIN;

    float acc[4][4][4];
#pragma unroll
    for (int i = 0; i < 4; i++)
#pragma unroll
        for (int j = 0; j < 4; j++)
#pragma unroll
            for (int k = 0; k < 4; k++) acc[i][j][k] = 0.f;

    float4 ra[4];
    uint4  rbh[2], rbl[2];

#define LDG_CHUNK(kc) {                                                        \
    int k0 = (kc) * 32;                                                        \
    ra[0] = *(const float4*)(Af + (size_t)rA[0] * DIN + k0 + qA[0] * 4);       \
    ra[1] = *(const float4*)(Af + (size_t)rA[1] * DIN + k0 + qA[1] * 4);       \
    ra[2] = *(const float4*)(Af + (size_t)rA[2] * DIN + k0 + qA[2] * 4);       \
    ra[3] = *(const float4*)(Af + (size_t)rA[3] * DIN + k0 + qA[3] * 4);       \
    rbh[0] = *(const uint4*)(Bh + (size_t)r0 * DIN + k0 + q0 * 8);             \
    rbh[1] = *(const uint4*)(Bh + (size_t)r1 * DIN + k0 + q1 * 8);             \
    rbl[0] = *(const uint4*)(Bl + (size_t)r0 * DIN + k0 + q0 * 8);             \
    rbl[1] = *(const uint4*)(Bl + (size_t)r1 * DIN + k0 + q1 * 8); }

#define STS_CHUNK(buf) {                                                       \
    char* sb = smem + (buf) * BUF_BYTES;                                       \
    _Pragma("unroll")                                                          \
    for (int i = 0; i < 4; i++) {                                              \
        __nv_bfloat16 h0, h1, h2, h3, l0, l1, l2, l3;                          \
        split1(ra[i].x, h0, l0); split1(ra[i].y, h1, l1);                      \
        split1(ra[i].z, h2, l2); split1(ra[i].w, h3, l3);                      \
        uint2 hv; hv.x = pack2(h0, h1); hv.y = pack2(h2, h3);                  \
        uint2 lv; lv.x = pack2(l0, l1); lv.y = pack2(l2, l3);                  \
        *(uint2*)(sb + rA[i] * 80 + qA[i] * 8)               = hv;             \
        *(uint2*)(sb + SPLIT_BYTES + rA[i] * 80 + qA[i] * 8) = lv;             \
    }                                                                          \
    *(uint4*)(sb + 2 * SPLIT_BYTES + r0 * 80 + q0 * 16)  = rbh[0];             \
    *(uint4*)(sb + 2 * SPLIT_BYTES + r1 * 80 + q1 * 16)  = rbh[1];             \
    *(uint4*)(sb + 3 * SPLIT_BYTES + r0 * 80 + q0 * 16)  = rbl[0];             \
    *(uint4*)(sb + 3 * SPLIT_BYTES + r1 * 80 + q1 * 16)  = rbl[1]; }

    LDG_CHUNK(0);
    STS_CHUNK(0);
    __syncthreads();

    for (int c = 0; c < 16; c++) {
        int buf = c & 1;
        if (c < 15) LDG_CHUNK(c + 1);

        uint32_t abase = sbase + buf * BUF_BYTES + aOff;
        uint32_t bbase = sbase + buf * BUF_BYTES + bOff;
#pragma unroll
        for (int kk = 0; kk < 2; kk++) {
            uint32_t kb = kk * 32;
            uint32_t fah[4][4], fbh[2][4];
#pragma unroll
            for (int mi = 0; mi < 4; mi++)
                ldsm4(fah[mi], abase + mi * 1280 + kb);
#pragma unroll
            for (int j2 = 0; j2 < 2; j2++)
                ldsm4(fbh[j2], bbase + j2 * 1280 + kb);
#pragma unroll
            for (int mi = 0; mi < 4; mi++)
#pragma unroll
                for (int nj = 0; nj < 4; nj++)
                    mma16816(acc[mi][nj], fah[mi],
                             fbh[nj >> 1][(nj & 1) * 2], fbh[nj >> 1][(nj & 1) * 2 + 1]);
            uint32_t fbl[2][4];
#pragma unroll
            for (int j2 = 0; j2 < 2; j2++)
                ldsm4(fbl[j2], bbase + SPLIT_BYTES + j2 * 1280 + kb);
#pragma unroll
            for (int mi = 0; mi < 4; mi++)
#pragma unroll
                for (int nj = 0; nj < 4; nj++)
                    mma16816(acc[mi][nj], fah[mi],
                             fbl[nj >> 1][(nj & 1) * 2], fbl[nj >> 1][(nj & 1) * 2 + 1]);
            uint32_t fal[4][4];
#pragma unroll
            for (int mi = 0; mi < 4; mi++)
                ldsm4(fal[mi], abase + SPLIT_BYTES + mi * 1280 + kb);
#pragma unroll
            for (int mi = 0; mi < 4; mi++)
#pragma unroll
                for (int nj = 0; nj < 4; nj++)
                    mma16816(acc[mi][nj], fal[mi],
                             fbh[nj >> 1][(nj & 1) * 2], fbh[nj >> 1][(nj & 1) * 2 + 1]);
        }

        if (c < 15) {
            STS_CHUNK(buf ^ 1);
            __syncthreads();
        }
    }

#pragma unroll
    for (int mi = 0; mi < 4; mi++) {
        int row = bm * 128 + wm + mi * 16 + (l >> 2);
#pragma unroll
        for (int nj = 0; nj < 4; nj++) {
            int col = bn * 128 + wn + nj * 8 + 2 * (l & 3);
            float2 bv = *(const float2*)&bias[col];
            float2 v0 = make_float2(acc[mi][nj][0] + bv.x, acc[mi][nj][1] + bv.y);
            float2 v1 = make_float2(acc[mi][nj][2] + bv.x, acc[mi][nj][3] + bv.y);
            *(float2*)&g_gates[(size_t)row * G3 + col]       = v0;
            *(float2*)&g_gates[(size_t)(row + 8) * G3 + col] = v1;
        }
    }
}

// ---------------- mma.sync persistent scan ----------------
// 128 blocks (bx=bid&3: 32 batches; by=bid>>2: 16 hh). Per step:
//   C[32 b][48 c] = Hs[32 b][512 k] * Ws[48 c][512 k]^T  (bf16 hi/lo split, 3 products)
#define HROWB   1040
#define A_HI    0
#define A_LO    33280
#define B_HI    66560
#define B_LO    116480
#define RED_OFF 166400
#define SCAN_SMEM (RED_OFF + 8 * 768 * 4)   // 190976

__global__ __launch_bounds__(256)
void scan_mma_kernel(const float* __restrict__ carry,
                     const void*  __restrict__ resets,
                     float* __restrict__ outputs,
                     float* __restrict__ carry_out) {
    extern __shared__ char smem[];
    uint32_t sbase = smem_u32(smem);

    int t = threadIdx.x, l = t & 31, wid = t >> 5;
    int kw = wid & 3, mw = wid >> 2;
    int bid = blockIdx.x;
    int bx = bid & 3, by = bid >> 2;
    int b0 = bx * 32;
    int hh0g = by * 16;
    int mode = g_reset_mode;

    const unsigned char* rbytes = (const unsigned char*)resets;
    const int*           rints  = (const int*)resets;

    // ---- one-time: W slices into smem ----
    {
        const char* wg = (const char*)g_Wh16;
#pragma unroll
        for (int sp = 0; sp < 2; sp++) {
            size_t gbase = ((size_t)sp * 32 + by) * 48 * DIN * 2;
#pragma unroll
            for (int i = 0; i < 12; i++) {
                int u = t + i * 256;
                int row = u >> 6, off = (u & 63) * 16;
                *(uint4*)(smem + B_HI + sp * 49920 + row * HROWB + off) =
                    *(const uint4*)(wg + gbase + (size_t)row * 1024 + off);
            }
        }
    }

    uint32_t aoff = sbase + A_HI +
        (uint32_t)((mw * 16 + (l & 7) + ((l >> 3) & 1) * 8) * HROWB + ((l >> 4) * 8) * 2);
    uint32_t boff = sbase + B_HI +
        (uint32_t)(((l & 7) + ((l >> 4) * 8)) * HROWB + (((l >> 3) & 1) * 8) * 2);

    int srow = t >> 3, scoff = (t & 7) * 128;

    int eb = t >> 3, ehh0 = (t & 7) * 2;
    int gb = b0 + eb;
    int ghh = hh0g + ehh0;
    int emw = eb >> 4, erow8 = (eb >> 3) & 1, erowl = eb & 7;

    float hp0 = carry[(size_t)gb * HDIM + ghh];
    float hp1 = carry[(size_t)gb * HDIM + ghh + 1];

    float* redf = (float*)(smem + RED_OFF);
    __syncthreads();   // W staged

    for (int s = 0; s < SEQ; s++) {
        int par = s & 1;

        size_t grow = ((size_t)s * BATCH + gb) * G3;
        float2 gz = *(const float2*)&g_gates[grow + ghh];
        float2 gr = *(const float2*)&g_gates[grow + HDIM + ghh];
        float2 gn = *(const float2*)&g_gates[grow + 2 * HDIM + ghh];
        bool ers = (mode == 0) ? (rints[s * BATCH + gb] != 0)
                               : (rbytes[s * BATCH + gb] != 0);
        float em = ers ? 0.f : 1.f;
        bool srs = (mode == 0) ? (rints[s * BATCH + b0 + srow] != 0)
                               : (rbytes[s * BATCH + b0 + srow] != 0);

        if (s > 0) {
            if (l == 0) {
                unsigned* cp = &g_done[(s - 1) * 4 + bx];
                while (ld_acq(cp) < 32u) { }
            }
            __syncwarp();
        }

        // ---- stage H (masked) ----
        {
            char* shi = smem + A_HI + srow * HROWB + scoff;
            char* slo = smem + A_LO + srow * HROWB + scoff;
            if (srs) {
                uint4 z = make_uint4(0, 0, 0, 0);
#pragma unroll
                for (int i = 0; i < 8; i++) {
                    *(uint4*)(shi + i * 16) = z;
                    *(uint4*)(slo + i * 16) = z;
                }
            } else if (s == 0) {
                // convert fp32 carry inline (prep_h0 eliminated)
                const float* cp = carry + (size_t)(b0 + srow) * HDIM + (t & 7) * 64;
#pragma unroll
                for (int i = 0; i < 16; i++) {
                    float4 v = *(const float4*)(cp + i * 4);
                    __nv_bfloat16 h0, h1, h2, h3, l0, l1, l2, l3;
                    split1(v.x, h0, l0); split1(v.y, h1, l1);
                    split1(v.z, h2, l2); split1(v.w, h3, l3);
                    uint2 hv; hv.x = pack2(h0, h1); hv.y = pack2(h2, h3);
                    uint2 lv; lv.x = pack2(l0, l1); lv.y = pack2(l2, l3);
                    *(uint2*)(shi + i * 8) = hv;
                    *(uint2*)(slo + i * 8) = lv;
                }
            } else {
                const char* ghi = (const char*)&g_h16[par][0][(size_t)(b0 + srow) * HDIM] + scoff;
                const char* glo = (const char*)&g_h16[par][1][(size_t)(b0 + srow) * HDIM] + scoff;
#pragma unroll
                for (int i = 0; i < 8; i++) {
                    *(uint4*)(shi + i * 16) = *(const uint4*)(ghi + i * 16);
                    *(uint4*)(slo + i * 16) = *(const uint4*)(glo + i * 16);
                }
            }
        }
        __syncthreads();

        // ---- mma over this warp's K range ----
        float acc[6][4];
#pragma unroll
        for (int i = 0; i < 6; i++)
#pragma unroll
            for (int j = 0; j < 4; j++) acc[i][j] = 0.f;

#pragma unroll
        for (int kt = 0; kt < 8; kt++) {
            uint32_t kb = (uint32_t)(kw * 256 + kt * 32);
            uint32_t fah[4], fal[4], fbh[3][4], fbl[3][4];
            ldsm4(fah, aoff + kb);
            ldsm4(fal, aoff + A_LO + kb);
#pragma unroll
            for (int j2 = 0; j2 < 3; j2++) {
                ldsm4(fbh[j2], boff + j2 * 16640 + kb);
                ldsm4(fbl[j2], boff + 49920 + j2 * 16640 + kb);
            }
#pragma unroll
            for (int j2 = 0; j2 < 3; j2++)
#pragma unroll
                for (int sub = 0; sub < 2; sub++) {
                    int nt = j2 * 2 + sub;
                    mma16816(acc[nt], fah, fbh[j2][sub * 2], fbh[j2][sub * 2 + 1]);
                    mma16816(acc[nt], fah, fbl[j2][sub * 2], fbl[j2][sub * 2 + 1]);
                    mma16816(acc[nt], fal, fbh[j2][sub * 2], fbh[j2][sub * 2 + 1]);
                }
        }

        // ---- cross-warp reduction via smem ----
        {
            float* rw = redf + wid * 768;
#pragma unroll
            for (int nt = 0; nt < 6; nt++)
#pragma unroll
                for (int c = 0; c < 4; c++)
                    rw[(nt * 4 + c) * 32 + l] = acc[nt][c];
        }
        __syncthreads();

        // ---- epilogue: 2 h values per thread ----
        float hn[2];
#pragma unroll
        for (int q = 0; q < 2; q++) {
            int hh = ehh0 + q;
            int nt01 = hh >> 3, hl = hh & 7;
            int lane = erowl * 4 + (hl >> 1);
            int creg = erow8 * 2 + (hh & 1);
            float sz = 0.f, sr = 0.f, sn = 0.f;
#pragma unroll
            for (int kwp = 0; kwp < 4; kwp++) {
                const float* rb = redf + (emw * 4 + kwp) * 768;
                sz += rb[((0 * 2 + nt01) * 4 + creg) * 32 + lane];
                sr += rb[((1 * 2 + nt01) * 4 + creg) * 32 + lane];
                sn += rb[((2 * 2 + nt01) * 4 + creg) * 32 + lane];
            }
            float giz = q ? gz.y : gz.x;
            float gir = q ? gr.y : gr.x;
            float gin = q ? gn.y : gn.x;
            float hp  = q ? hp1 : hp0;
            float z = 1.f / (1.f + __expf(-(giz + sz)));
            float r = 1.f / (1.f + __expf(-(gir + sr)));
            float n = tanhf(gin + r * sn);
            hn[q] = (1.f - z) * n + z * (hp * em);
        }
        hp0 = hn[0]; hp1 = hn[1];

        *(float2*)&outputs[((size_t)s * BATCH + gb) * HDIM + ghh] = make_float2(hn[0], hn[1]);
        {
            __nv_bfloat16 h0, h1, l0, l1;
            split1(hn[0], h0, l0);
            split1(hn[1], h1, l1);
            *(uint32_t*)&g_h16[par ^ 1][0][(size_t)gb * HDIM + ghh] = pack2(h0, h1);
            *(uint32_t*)&g_h16[par ^ 1][1][(size_t)gb * HDIM + ghh] = pack2(l0, l1);
        }
        if (carry_out && s == SEQ - 1)
            *(float2*)&carry_out[(size_t)gb * HDIM + ghh] = make_float2(hn[0], hn[1]);

        __syncthreads();
        if (t == 0 && s < SEQ - 1) red_rel(&g_done[s * 4 + bx]);
    }
}

// ---------------- launcher ----------------
extern "C" void kernel_launch(void* const* d_in, const int* in_sizes, int n_in,
                              void* d_out, int out_size) {
    const float* carry = (const float*)d_in[0];
    const float* ins   = (const float*)d_in[1];
    const void*  rsts  = d_in[2];
    const float* W_in  = (const float*)d_in[3];
    const float* b_in  = (const float*)d_in[4];
    const float* W_h   = (const float*)d_in[5];

    float* out = (float*)d_out;
    float* carry_out;
    float* outputs;
    if (out_size == (int)((size_t)SEQ * BATCH * HDIM)) {
        carry_out = nullptr;
        outputs   = out;
    } else {
        carry_out = out;
        outputs   = out + (size_t)BATCH * HDIM;
    }

    cudaFuncSetAttribute(gates_mma_kernel,
                         cudaFuncAttributeMaxDynamicSharedMemorySize, GEMM_SMEM);
    cudaFuncSetAttribute(scan_mma_kernel,
                         cudaFuncAttributeMaxDynamicSharedMemorySize, SCAN_SMEM);

    init_kernel<<<2, 256>>>((const unsigned int*)rsts);
    prep_w_kernel<<<(G3 * DIN + 255) / 256, 256>>>(W_in);
    prep_wh_kernel<<<(32 * 48 * DIN + 255) / 256, 256>>>(W_h);
    gates_mma_kernel<<<dim3(G3 / 128, MROWS / 128), 256, GEMM_SMEM>>>(ins, b_in);
    scan_mma_kernel<<<128, 256, SCAN_SMEM>>>(carry, rsts, outputs, carry_out);
}

// round 11
// speedup vs baseline: 2.3687x; 1.0232x over previous
#include <cuda_runtime.h>
#include <cuda_bf16.h>
#include <math.h>
#include <stdint.h>

#define SEQ   512
#define BATCH 128
#define DIN   512
#define HDIM  512
#define G3    1536
#define MROWS (SEQ * BATCH)        // 65536

// ---------------- scratch (device globals) ----------------
__device__ float g_gates[(size_t)SEQ * BATCH * G3];          // ~402MB
__device__ __nv_bfloat16 g_Bhi[(size_t)G3 * DIN];            // W_in^T hi [n][k]
__device__ __nv_bfloat16 g_Blo[(size_t)G3 * DIN];            // W_in^T lo [n][k]
__device__ __nv_bfloat16 g_Wh16[(size_t)2 * 32 * 48 * DIN];  // W_h split [split][by][c][k]
__device__ __nv_bfloat16 g_h16[2][2][(size_t)BATCH * HDIM];  // [parity][split][b*512+hh]
__device__ int      g_reset_mode;
__device__ unsigned g_done[SEQ * 4];                         // per-(step,bx) counters

// ---------------- mma.sync helpers ----------------
__device__ __forceinline__ uint32_t smem_u32(const void* p) {
    return (uint32_t)__cvta_generic_to_shared(p);
}
__device__ __forceinline__ void ldsm4(uint32_t* r, uint32_t addr) {
    asm volatile("ldmatrix.sync.aligned.m8n8.x4.shared.b16 {%0,%1,%2,%3}, [%4];"
                 : "=r"(r[0]), "=r"(r[1]), "=r"(r[2]), "=r"(r[3]) : "r"(addr));
}
__device__ __forceinline__ void mma16816(float* c, const uint32_t* a,
                                         uint32_t b0, uint32_t b1) {
    asm volatile(
        "mma.sync.aligned.m16n8k16.row.col.f32.bf16.bf16.f32 "
        "{%0,%1,%2,%3}, {%4,%5,%6,%7}, {%8,%9}, {%0,%1,%2,%3};"
        : "+f"(c[0]), "+f"(c[1]), "+f"(c[2]), "+f"(c[3])
        : "r"(a[0]), "r"(a[1]), "r"(a[2]), "r"(a[3]), "r"(b0), "r"(b1));
}
__device__ __forceinline__ unsigned ld_acq(const unsigned* p) {
    unsigned v;
    asm volatile("ld.acquire.gpu.global.u32 %0, [%1];" : "=r"(v) : "l"(p) : "memory");
    return v;
}
__device__ __forceinline__ void red_rel(unsigned* p) {
    asm volatile("red.release.gpu.global.add.u32 [%0], 1;" :: "l"(p) : "memory");
}
__device__ __forceinline__ void cp_async16(uint32_t saddr, const void* g) {
    asm volatile("cp.async.cg.shared.global [%0], [%1], 16;" :: "r"(saddr), "l"(g));
}
#define CP_COMMIT() asm volatile("cp.async.commit_group;" ::: "memory")
#define CP_WAIT0()  asm volatile("cp.async.wait_group 0;" ::: "memory")

// pack two bf16 into a uint32 (low = first)
__device__ __forceinline__ uint32_t pack2(__nv_bfloat16 a, __nv_bfloat16 b) {
    __nv_bfloat162 v; v.x = a; v.y = b;
    return *(uint32_t*)&v;
}
// split one float into (hi, lo) bf16
__device__ __forceinline__ void split1(float x, __nv_bfloat16& h, __nv_bfloat16& l) {
    h = __float2bfloat16(x);
    l = __float2bfloat16(x - __bfloat162float(h));
}

// ---------------- init + reset dtype sniffing ----------------
__global__ void init_kernel(const unsigned int* __restrict__ r) {
    int t = blockIdx.x * 256 + threadIdx.x;
    for (int i = t; i < SEQ * 4; i += 512) g_done[i] = 0u;
    if (t == 0) {
        bool word_mode = true;
        for (int i = 0; i < 64; i++) {
            unsigned v = r[i];
            if (!(v == 0u || v == 1u || v == 0x3F800000u)) { word_mode = false; break; }
        }
        g_reset_mode = word_mode ? 0 : 2;
    }
}

// ---------------- prep kernels ----------------
__global__ void prep_w_kernel(const float* __restrict__ W) {
    int idx = blockIdx.x * 256 + threadIdx.x;
    if (idx < G3 * DIN) {
        int n = idx >> 9, k = idx & 511;
        float x = W[(size_t)k * G3 + n];
        __nv_bfloat16 h, l;
        split1(x, h, l);
        g_Bhi[idx] = h;
        g_Blo[idx] = l;
    }
}
// W_h split: [split][by][c(0..47)][k];  c: 0-15 z, 16-31 r, 32-47 n; hh = by*16 + (c&15)
__global__ void prep_wh_kernel(const float* __restrict__ Wh) {
    int idx = blockIdx.x * 256 + threadIdx.x;   // over 32*48*512
    if (idx < 32 * 48 * DIN) {
        int k  = idx & 511;
        int c  = (idx >> 9) % 48;
        int by = idx / (48 * DIN);
        int j  = c >> 4;
        int hh = by * 16 + (c & 15);
        float x = Wh[(size_t)k * G3 + j * HDIM + hh];
        __nv_bfloat16 h, l;
        split1(x, h, l);
        size_t o = ((size_t)by * 48 + c) * DIN + k;
        g_Wh16[o] = h;
        g_Wh16[(size_t)32 * 48 * DIN + o] = l;
    }
}

// ---------------- mma.sync gates GEMM (cp.async B, 2 CTAs/SM) ----------------
#define TROW 40
#define SPLIT_BYTES 10240
#define BUF_BYTES   40960
#define GEMM_SMEM   (2 * BUF_BYTES)

__global__ __launch_bounds__(256, 2)
void gates_mma_kernel(const float* __restrict__ A,      // ins fp32 [65536][512]
                      const float* __restrict__ bias) {
    extern __shared__ char smem[];
    uint32_t sbase = smem_u32(smem);

    int t = threadIdx.x, l = t & 31, wid = t >> 5;
    int bn = blockIdx.x, bm = blockIdx.y;
    int wm = (wid & 1) * 64, wn = (wid >> 1) * 32;

    uint32_t aOff = ((wm + (l & 7) + ((l >> 3) & 1) * 8) * TROW + ((l >> 4) * 8)) * 2;
    uint32_t bOff = 2 * SPLIT_BYTES +
                    ((wn + (l & 7) + ((l >> 4) * 8)) * TROW + (((l >> 3) & 1) * 8)) * 2;

    // A staging (fp32): 128 rows x 32 k = 1024 float4 units; 4 per thread
    int rA[4], qA[4];
#pragma unroll
    for (int i = 0; i < 4; i++) { int u = t + i * 256; rA[i] = u >> 3; qA[i] = u & 7; }
    // B staging (bf16, cp.async): 512 uint4 units per split; 2 per thread
    int u0 = t, u1 = t + 256;
    int r0 = u0 >> 2, q0 = u0 & 3;
    int r1 = u1 >> 2, q1 = u1 & 3;

    const float*         Af = A     + (size_t)(bm * 128) * DIN;
    const __nv_bfloat16* Bh = g_Bhi + (size_t)(bn * 128) * DIN;
    const __nv_bfloat16* Bl = g_Blo + (size_t)(bn * 128) * DIN;

    float acc[4][4][4];
#pragma unroll
    for (int i = 0; i < 4; i++)
#pragma unroll
        for (int j = 0; j < 4; j++)
#pragma unroll
            for (int k = 0; k < 4; k++) acc[i][j][k] = 0.f;

    float4 ra[4];

#define LDG_A(kc) {                                                            \
    int k0 = (kc) * 32;                                                        \
    ra[0] = *(const float4*)(Af + (size_t)rA[0] * DIN + k0 + qA[0] * 4);       \
    ra[1] = *(const float4*)(Af + (size_t)rA[1] * DIN + k0 + qA[1] * 4);       \
    ra[2] = *(const float4*)(Af + (size_t)rA[2] * DIN + k0 + qA[2] * 4);       \
    ra[3] = *(const float4*)(Af + (size_t)rA[3] * DIN + k0 + qA[3] * 4); }

#define CPB(kc, buf) {                                                         \
    int k0 = (kc) * 32;                                                        \
    uint32_t sb = sbase + (buf) * BUF_BYTES;                                   \
    cp_async16(sb + 2 * SPLIT_BYTES + r0 * 80 + q0 * 16,                       \
               Bh + (size_t)r0 * DIN + k0 + q0 * 8);                           \
    cp_async16(sb + 2 * SPLIT_BYTES + r1 * 80 + q1 * 16,                       \
               Bh + (size_t)r1 * DIN + k0 + q1 * 8);                           \
    cp_async16(sb + 3 * SPLIT_BYTES + r0 * 80 + q0 * 16,                       \
               Bl + (size_t)r0 * DIN + k0 + q0 * 8);                           \
    cp_async16(sb + 3 * SPLIT_BYTES + r1 * 80 + q1 * 16,                       \
               Bl + (size_t)r1 * DIN + k0 + q1 * 8);                           \
    CP_COMMIT(); }

#define STS_A(buf) {                                                           \
    char* sb = smem + (buf) * BUF_BYTES;                                       \
    _Pragma("unroll")                                                          \
    for (int i = 0; i < 4; i++) {                                              \
        __nv_bfloat16 h0, h1, h2, h3, l0, l1, l2, l3;                          \
        split1(ra[i].x, h0, l0); split1(ra[i].y, h1, l1);                      \
        split1(ra[i].z, h2, l2); split1(ra[i].w, h3, l3);                      \
        uint2 hv; hv.x = pack2(h0, h1); hv.y = pack2(h2, h3);                  \
        uint2 lv; lv.x = pack2(l0, l1); lv.y = pack2(l2, l3);                  \
        *(uint2*)(sb + rA[i] * 80 + qA[i] * 8)               = hv;             \
        *(uint2*)(sb + SPLIT_BYTES + rA[i] * 80 + qA[i] * 8) = lv;             \
    } }

    // prologue: chunk 0 into buf 0
    CPB(0, 0);
    LDG_A(0);
    STS_A(0);
    CP_WAIT0();
    __syncthreads();

    for (int c = 0; c < 16; c++) {
        int buf = c & 1;
        if (c < 15) {
            CPB(c + 1, buf ^ 1);    // B latency hides under the mma section
            LDG_A(c + 1);
        }

        uint32_t abase = sbase + buf * BUF_BYTES + aOff;
        uint32_t bbase = sbase + buf * BUF_BYTES + bOff;
#pragma unroll
        for (int kk = 0; kk < 2; kk++) {
            uint32_t kb = kk * 32;
            uint32_t fah[4][4], fbh[2][4];
#pragma unroll
            for (int mi = 0; mi < 4; mi++)
                ldsm4(fah[mi], abase + mi * 1280 + kb);
#pragma unroll
            for (int j2 = 0; j2 < 2; j2++)
                ldsm4(fbh[j2], bbase + j2 * 1280 + kb);
#pragma unroll
            for (int mi = 0; mi < 4; mi++)
#pragma unroll
                for (int nj = 0; nj < 4; nj++)
                    mma16816(acc[mi][nj], fah[mi],
                             fbh[nj >> 1][(nj & 1) * 2], fbh[nj >> 1][(nj & 1) * 2 + 1]);
            uint32_t fbl[2][4];
#pragma unroll
            for (int j2 = 0; j2 < 2; j2++)
                ldsm4(fbl[j2], bbase + SPLIT_BYTES + j2 * 1280 + kb);
#pragma unroll
            for (int mi = 0; mi < 4; mi++)
#pragma unroll
                for (int nj = 0; nj < 4; nj++)
                    mma16816(acc[mi][nj], fah[mi],
                             fbl[nj >> 1][(nj & 1) * 2], fbl[nj >> 1][(nj & 1) * 2 + 1]);
            uint32_t fal[4][4];
#pragma unroll
            for (int mi = 0; mi < 4; mi++)
                ldsm4(fal[mi], abase + SPLIT_BYTES + mi * 1280 + kb);
#pragma unroll
            for (int mi = 0; mi < 4; mi++)
#pragma unroll
                for (int nj = 0; nj < 4; nj++)
                    mma16816(acc[mi][nj], fal[mi],
                             fbh[nj >> 1][(nj & 1) * 2], fbh[nj >> 1][(nj & 1) * 2 + 1]);
        }

        if (c < 15) {
            STS_A(buf ^ 1);
            CP_WAIT0();
            __syncthreads();
        }
    }

#pragma unroll
    for (int mi = 0; mi < 4; mi++) {
        int row = bm * 128 + wm + mi * 16 + (l >> 2);
#pragma unroll
        for (int nj = 0; nj < 4; nj++) {
            int col = bn * 128 + wn + nj * 8 + 2 * (l & 3);
            float2 bv = *(const float2*)&bias[col];
            float2 v0 = make_float2(acc[mi][nj][0] + bv.x, acc[mi][nj][1] + bv.y);
            float2 v1 = make_float2(acc[mi][nj][2] + bv.x, acc[mi][nj][3] + bv.y);
            *(float2*)&g_gates[(size_t)row * G3 + col]       = v0;
            *(float2*)&g_gates[(size_t)(row + 8) * G3 + col] = v1;
        }
    }
}

// ---------------- mma.sync persistent scan (round-9/10, unchanged) ----------------
#define HROWB   1040
#define A_HI    0
#define A_LO    33280
#define B_HI    66560
#define B_LO    116480
#define RED_OFF 166400
#define SCAN_SMEM (RED_OFF + 8 * 768 * 4)   // 190976

__global__ __launch_bounds__(256)
void scan_mma_kernel(const float* __restrict__ carry,
                     const void*  __restrict__ resets,
                     float* __restrict__ outputs,
                     float* __restrict__ carry_out) {
    extern __shared__ char smem[];
    uint32_t sbase = smem_u32(smem);

    int t = threadIdx.x, l = t & 31, wid = t >> 5;
    int kw = wid & 3, mw = wid >> 2;
    int bid = blockIdx.x;
    int bx = bid & 3, by = bid >> 2;
    int b0 = bx * 32;
    int hh0g = by * 16;
    int mode = g_reset_mode;

    const unsigned char* rbytes = (const unsigned char*)resets;
    const int*           rints  = (const int*)resets;

    // ---- one-time: W slices into smem ----
    {
        const char* wg = (const char*)g_Wh16;
#pragma unroll
        for (int sp = 0; sp < 2; sp++) {
            size_t gbase = ((size_t)sp * 32 + by) * 48 * DIN * 2;
#pragma unroll
            for (int i = 0; i < 12; i++) {
                int u = t + i * 256;
                int row = u >> 6, off = (u & 63) * 16;
                *(uint4*)(smem + B_HI + sp * 49920 + row * HROWB + off) =
                    *(const uint4*)(wg + gbase + (size_t)row * 1024 + off);
            }
        }
    }

    uint32_t aoff = sbase + A_HI +
        (uint32_t)((mw * 16 + (l & 7) + ((l >> 3) & 1) * 8) * HROWB + ((l >> 4) * 8) * 2);
    uint32_t boff = sbase + B_HI +
        (uint32_t)(((l & 7) + ((l >> 4) * 8)) * HROWB + (((l >> 3) & 1) * 8) * 2);

    int srow = t >> 3, scoff = (t & 7) * 128;

    int eb = t >> 3, ehh0 = (t & 7) * 2;
    int gb = b0 + eb;
    int ghh = hh0g + ehh0;
    int emw = eb >> 4, erow8 = (eb >> 3) & 1, erowl = eb & 7;

    float hp0 = carry[(size_t)gb * HDIM + ghh];
    float hp1 = carry[(size_t)gb * HDIM + ghh + 1];

    float* redf = (float*)(smem + RED_OFF);
    __syncthreads();   // W staged

    for (int s = 0; s < SEQ; s++) {
        int par = s & 1;

        size_t grow = ((size_t)s * BATCH + gb) * G3;
        float2 gz = *(const float2*)&g_gates[grow + ghh];
        float2 gr = *(const float2*)&g_gates[grow + HDIM + ghh];
        float2 gn = *(const float2*)&g_gates[grow + 2 * HDIM + ghh];
        bool ers = (mode == 0) ? (rints[s * BATCH + gb] != 0)
                               : (rbytes[s * BATCH + gb] != 0);
        float em = ers ? 0.f : 1.f;
        bool srs = (mode == 0) ? (rints[s * BATCH + b0 + srow] != 0)
                               : (rbytes[s * BATCH + b0 + srow] != 0);

        if (s > 0) {
            if (l == 0) {
                unsigned* cp = &g_done[(s - 1) * 4 + bx];
                while (ld_acq(cp) < 32u) { }
            }
            __syncwarp();
        }

        // ---- stage H (masked) ----
        {
            char* shi = smem + A_HI + srow * HROWB + scoff;
            char* slo = smem + A_LO + srow * HROWB + scoff;
            if (srs) {
                uint4 z = make_uint4(0, 0, 0, 0);
#pragma unroll
                for (int i = 0; i < 8; i++) {
                    *(uint4*)(shi + i * 16) = z;
                    *(uint4*)(slo + i * 16) = z;
                }
            } else if (s == 0) {
                const float* cp = carry + (size_t)(b0 + srow) * HDIM + (t & 7) * 64;
#pragma unroll
                for (int i = 0; i < 16; i++) {
                    float4 v = *(const float4*)(cp + i * 4);
                    __nv_bfloat16 h0, h1, h2, h3, l0, l1, l2, l3;
                    split1(v.x, h0, l0); split1(v.y, h1, l1);
                    split1(v.z, h2, l2); split1(v.w, h3, l3);
                    uint2 hv; hv.x = pack2(h0, h1); hv.y = pack2(h2, h3);
                    uint2 lv; lv.x = pack2(l0, l1); lv.y = pack2(l2, l3);
                    *(uint2*)(shi + i * 8) = hv;
                    *(uint2*)(slo + i * 8) = lv;
                }
            } else {
                const char* ghi = (const char*)&g_h16[par][0][(size_t)(b0 + srow) * HDIM] + scoff;
                const char* glo = (const char*)&g_h16[par][1][(size_t)(b0 + srow) * HDIM] + scoff;
#pragma unroll
                for (int i = 0; i < 8; i++) {
                    *(uint4*)(shi + i * 16) = *(const uint4*)(ghi + i * 16);
                    *(uint4*)(slo + i * 16) = *(const uint4*)(glo + i * 16);
                }
            }
        }
        __syncthreads();

        // ---- mma over this warp's K range ----
        float acc[6][4];
#pragma unroll
        for (int i = 0; i < 6; i++)
#pragma unroll
            for (int j = 0; j < 4; j++) acc[i][j] = 0.f;

#pragma unroll
        for (int kt = 0; kt < 8; kt++) {
            uint32_t kb = (uint32_t)(kw * 256 + kt * 32);
            uint32_t fah[4], fal[4], fbh[3][4], fbl[3][4];
            ldsm4(fah, aoff + kb);
            ldsm4(fal, aoff + A_LO + kb);
#pragma unroll
            for (int j2 = 0; j2 < 3; j2++) {
                ldsm4(fbh[j2], boff + j2 * 16640 + kb);
                ldsm4(fbl[j2], boff + 49920 + j2 * 16640 + kb);
            }
#pragma unroll
            for (int j2 = 0; j2 < 3; j2++)
#pragma unroll
                for (int sub = 0; sub < 2; sub++) {
                    int nt = j2 * 2 + sub;
                    mma16816(acc[nt], fah, fbh[j2][sub * 2], fbh[j2][sub * 2 + 1]);
                    mma16816(acc[nt], fah, fbl[j2][sub * 2], fbl[j2][sub * 2 + 1]);
                    mma16816(acc[nt], fal, fbh[j2][sub * 2], fbh[j2][sub * 2 + 1]);
                }
        }

        // ---- cross-warp reduction via smem ----
        {
            float* rw = redf + wid * 768;
#pragma unroll
            for (int nt = 0; nt < 6; nt++)
#pragma unroll
                for (int c = 0; c < 4; c++)
                    rw[(nt * 4 + c) * 32 + l] = acc[nt][c];
        }
        __syncthreads();

        // ---- epilogue: 2 h values per thread ----
        float hn[2];
#pragma unroll
        for (int q = 0; q < 2; q++) {
            int hh = ehh0 + q;
            int nt01 = hh >> 3, hl = hh & 7;
            int lane = erowl * 4 + (hl >> 1);
            int creg = erow8 * 2 + (hh & 1);
            float sz = 0.f, sr = 0.f, sn = 0.f;
#pragma unroll
            for (int kwp = 0; kwp < 4; kwp++) {
                const float* rb = redf + (emw * 4 + kwp) * 768;
                sz += rb[((0 * 2 + nt01) * 4 + creg) * 32 + lane];
                sr += rb[((1 * 2 + nt01) * 4 + creg) * 32 + lane];
                sn += rb[((2 * 2 + nt01) * 4 + creg) * 32 + lane];
            }
            float giz = q ? gz.y : gz.x;
            float gir = q ? gr.y : gr.x;
            float gin = q ? gn.y : gn.x;
            float hp  = q ? hp1 : hp0;
            float z = 1.f / (1.f + __expf(-(giz + sz)));
            float r = 1.f / (1.f + __expf(-(gir + sr)));
            float n = tanhf(gin + r * sn);
            hn[q] = (1.f - z) * n + z * (hp * em);
        }
        hp0 = hn[0]; hp1 = hn[1];

        *(float2*)&outputs[((size_t)s * BATCH + gb) * HDIM + ghh] = make_float2(hn[0], hn[1]);
        {
            __nv_bfloat16 h0, h1, l0, l1;
            split1(hn[0], h0, l0);
            split1(hn[1], h1, l1);
            *(uint32_t*)&g_h16[par ^ 1][0][(size_t)gb * HDIM + ghh] = pack2(h0, h1);
            *(uint32_t*)&g_h16[par ^ 1][1][(size_t)gb * HDIM + ghh] = pack2(l0, l1);
        }
        if (carry_out && s == SEQ - 1)
            *(float2*)&carry_out[(size_t)gb * HDIM + ghh] = make_float2(hn[0], hn[1]);

        __syncthreads();
        if (t == 0 && s < SEQ - 1) red_rel(&g_done[s * 4 + bx]);
    }
}

// ---------------- launcher ----------------
extern "C" void kernel_launch(void* const* d_in, const int* in_sizes, int n_in,
                              void* d_out, int out_size) {
    const float* carry = (const float*)d_in[0];
    const float* ins   = (const float*)d_in[1];
    const void*  rsts  = d_in[2];
    const float* W_in  = (const float*)d_in[3];
    const float* b_in  = (const float*)d_in[4];
    const float* W_h   = (const float*)d_in[5];

    float* out = (float*)d_out;
    float* carry_out;
    float* outputs;
    if (out_size == (int)((size_t)SEQ * BATCH * HDIM)) {
        carry_out = nullptr;
        outputs   = out;
    } else {
        carry_out = out;
        outputs   = out + (size_t)BATCH * HDIM;
    }

    cudaFuncSetAttribute(gates_mma_kernel,
                         cudaFuncAttributeMaxDynamicSharedMemorySize, GEMM_SMEM);
    cudaFuncSetAttribute(scan_mma_kernel,
                         cudaFuncAttributeMaxDynamicSharedMemorySize, SCAN_SMEM);

    init_kernel<<<2, 256>>>((const unsigned int*)rsts);
    prep_w_kernel<<<(G3 * DIN + 255) / 256, 256>>>(W_in);
    prep_wh_kernel<<<(32 * 48 * DIN + 255) / 256, 256>>>(W_h);
    gates_mma_kernel<<<dim3(G3 / 128, MROWS / 128), 256, GEMM_SMEM>>>(ins, b_in);
    scan_mma_kernel<<<128, 256, SCAN_SMEM>>>(carry, rsts, outputs, carry_out);
}

// round 12
// speedup vs baseline: 2.6279x; 1.1094x over previous
#include <cuda_runtime.h>
#include <cuda_bf16.h>
#include <math.h>
#include <stdint.h>

#define SEQ   512
#define BATCH 128
#define DIN   512
#define HDIM  512
#define G3    1536
#define MROWS (SEQ * BATCH)        // 65536

// ---------------- scratch (device globals) ----------------
__device__ float g_gates[(size_t)SEQ * BATCH * G3];          // ~402MB
__device__ __nv_bfloat16 g_Bhi[(size_t)G3 * DIN];            // W_in^T hi [n][k]
__device__ __nv_bfloat16 g_Blo[(size_t)G3 * DIN];            // W_in^T lo [n][k]
__device__ __nv_bfloat16 g_Wh16[(size_t)2 * 32 * 48 * DIN];  // W_h split [split][by][c][k]
__device__ __nv_bfloat16 g_h16[2][2][(size_t)BATCH * HDIM];  // [parity][split][b*512+hh]
__device__ int      g_reset_mode;
__device__ unsigned g_done[SEQ * 4];                         // per-(step,bx) counters

// ---------------- mma.sync helpers ----------------
__device__ __forceinline__ uint32_t smem_u32(const void* p) {
    return (uint32_t)__cvta_generic_to_shared(p);
}
__device__ __forceinline__ void ldsm4(uint32_t* r, uint32_t addr) {
    asm volatile("ldmatrix.sync.aligned.m8n8.x4.shared.b16 {%0,%1,%2,%3}, [%4];"
                 : "=r"(r[0]), "=r"(r[1]), "=r"(r[2]), "=r"(r[3]) : "r"(addr));
}
__device__ __forceinline__ void mma16816(float* c, const uint32_t* a,
                                         uint32_t b0, uint32_t b1) {
    asm volatile(
        "mma.sync.aligned.m16n8k16.row.col.f32.bf16.bf16.f32 "
        "{%0,%1,%2,%3}, {%4,%5,%6,%7}, {%8,%9}, {%0,%1,%2,%3};"
        : "+f"(c[0]), "+f"(c[1]), "+f"(c[2]), "+f"(c[3])
        : "r"(a[0]), "r"(a[1]), "r"(a[2]), "r"(a[3]), "r"(b0), "r"(b1));
}
__device__ __forceinline__ unsigned ld_acq(const unsigned* p) {
    unsigned v;
    asm volatile("ld.acquire.gpu.global.u32 %0, [%1];" : "=r"(v) : "l"(p) : "memory");
    return v;
}
__device__ __forceinline__ void red_rel(unsigned* p) {
    asm volatile("red.release.gpu.global.add.u32 [%0], 1;" :: "l"(p) : "memory");
}
__device__ __forceinline__ void cp_async16(uint32_t saddr, const void* g) {
    asm volatile("cp.async.cg.shared.global [%0], [%1], 16;" :: "r"(saddr), "l"(g));
}
#define CP_COMMIT() asm volatile("cp.async.commit_group;" ::: "memory")
#define CP_WAIT0()  asm volatile("cp.async.wait_group 0;" ::: "memory")

// pack two bf16 into a uint32 (low = first)
__device__ __forceinline__ uint32_t pack2(__nv_bfloat16 a, __nv_bfloat16 b) {
    __nv_bfloat162 v; v.x = a; v.y = b;
    return *(uint32_t*)&v;
}
// split one float into (hi, lo) bf16
__device__ __forceinline__ void split1(float x, __nv_bfloat16& h, __nv_bfloat16& l) {
    h = __float2bfloat16(x);
    l = __float2bfloat16(x - __bfloat162float(h));
}

// ---------------- init + reset dtype sniffing ----------------
__global__ void init_kernel(const unsigned int* __restrict__ r) {
    int t = blockIdx.x * 256 + threadIdx.x;
    for (int i = t; i < SEQ * 4; i += 512) g_done[i] = 0u;
    if (t == 0) {
        bool word_mode = true;
        for (int i = 0; i < 64; i++) {
            unsigned v = r[i];
            if (!(v == 0u || v == 1u || v == 0x3F800000u)) { word_mode = false; break; }
        }
        g_reset_mode = word_mode ? 0 : 2;
    }
}

// ---------------- prep kernels ----------------
__global__ void prep_w_kernel(const float* __restrict__ W) {
    int idx = blockIdx.x * 256 + threadIdx.x;
    if (idx < G3 * DIN) {
        int n = idx >> 9, k = idx & 511;
        float x = W[(size_t)k * G3 + n];
        __nv_bfloat16 h, l;
        split1(x, h, l);
        g_Bhi[idx] = h;
        g_Blo[idx] = l;
    }
}
// W_h split: [split][by][c(0..47)][k];  c: 0-15 z, 16-31 r, 32-47 n; hh = by*16 + (c&15)
__global__ void prep_wh_kernel(const float* __restrict__ Wh) {
    int idx = blockIdx.x * 256 + threadIdx.x;   // over 32*48*512
    if (idx < 32 * 48 * DIN) {
        int k  = idx & 511;
        int c  = (idx >> 9) % 48;
        int by = idx / (48 * DIN);
        int j  = c >> 4;
        int hh = by * 16 + (c & 15);
        float x = Wh[(size_t)k * G3 + j * HDIM + hh];
        __nv_bfloat16 h, l;
        split1(x, h, l);
        size_t o = ((size_t)by * 48 + c) * DIN + k;
        g_Wh16[o] = h;
        g_Wh16[(size_t)32 * 48 * DIN + o] = l;
    }
}

// ---------------- mma.sync gates GEMM (round-11, unchanged) ----------------
#define TROW 40
#define SPLIT_BYTES 10240
#define BUF_BYTES   40960
#define GEMM_SMEM   (2 * BUF_BYTES)

__global__ __launch_bounds__(256, 2)
void gates_mma_kernel(const float* __restrict__ A,      // ins fp32 [65536][512]
                      const float* __restrict__ bias) {
    extern __shared__ char smem[];
    uint32_t sbase = smem_u32(smem);

    int t = threadIdx.x, l = t & 31, wid = t >> 5;
    int bn = blockIdx.x, bm = blockIdx.y;
    int wm = (wid & 1) * 64, wn = (wid >> 1) * 32;

    uint32_t aOff = ((wm + (l & 7) + ((l >> 3) & 1) * 8) * TROW + ((l >> 4) * 8)) * 2;
    uint32_t bOff = 2 * SPLIT_BYTES +
                    ((wn + (l & 7) + ((l >> 4) * 8)) * TROW + (((l >> 3) & 1) * 8)) * 2;

    int rA[4], qA[4];
#pragma unroll
    for (int i = 0; i < 4; i++) { int u = t + i * 256; rA[i] = u >> 3; qA[i] = u & 7; }
    int u0 = t, u1 = t + 256;
    int r0 = u0 >> 2, q0 = u0 & 3;
    int r1 = u1 >> 2, q1 = u1 & 3;

    const float*         Af = A     + (size_t)(bm * 128) * DIN;
    const __nv_bfloat16* Bh = g_Bhi + (size_t)(bn * 128) * DIN;
    const __nv_bfloat16* Bl = g_Blo + (size_t)(bn * 128) * DIN;

    float acc[4][4][4];
#pragma unroll
    for (int i = 0; i < 4; i++)
#pragma unroll
        for (int j = 0; j < 4; j++)
#pragma unroll
            for (int k = 0; k < 4; k++) acc[i][j][k] = 0.f;

    float4 ra[4];

#define LDG_A(kc) {                                                            \
    int k0 = (kc) * 32;                                                        \
    ra[0] = *(const float4*)(Af + (size_t)rA[0] * DIN + k0 + qA[0] * 4);       \
    ra[1] = *(const float4*)(Af + (size_t)rA[1] * DIN + k0 + qA[1] * 4);       \
    ra[2] = *(const float4*)(Af + (size_t)rA[2] * DIN + k0 + qA[2] * 4);       \
    ra[3] = *(const float4*)(Af + (size_t)rA[3] * DIN + k0 + qA[3] * 4); }

#define CPB(kc, buf) {                                                         \
    int k0 = (kc) * 32;                                                        \
    uint32_t sb = sbase + (buf) * BUF_BYTES;                                   \
    cp_async16(sb + 2 * SPLIT_BYTES + r0 * 80 + q0 * 16,                       \
               Bh + (size_t)r0 * DIN + k0 + q0 * 8);                           \
    cp_async16(sb + 2 * SPLIT_BYTES + r1 * 80 + q1 * 16,                       \
               Bh + (size_t)r1 * DIN + k0 + q1 * 8);                           \
    cp_async16(sb + 3 * SPLIT_BYTES + r0 * 80 + q0 * 16,                       \
               Bl + (size_t)r0 * DIN + k0 + q0 * 8);                           \
    cp_async16(sb + 3 * SPLIT_BYTES + r1 * 80 + q1 * 16,                       \
               Bl + (size_t)r1 * DIN + k0 + q1 * 8);                           \
    CP_COMMIT(); }

#define STS_A(buf) {                                                           \
    char* sb = smem + (buf) * BUF_BYTES;                                       \
    _Pragma("unroll")                                                          \
    for (int i = 0; i < 4; i++) {                                              \
        __nv_bfloat16 h0, h1, h2, h3, l0, l1, l2, l3;                          \
        split1(ra[i].x, h0, l0); split1(ra[i].y, h1, l1);                      \
        split1(ra[i].z, h2, l2); split1(ra[i].w, h3, l3);                      \
        uint2 hv; hv.x = pack2(h0, h1); hv.y = pack2(h2, h3);                  \
        uint2 lv; lv.x = pack2(l0, l1); lv.y = pack2(l2, l3);                  \
        *(uint2*)(sb + rA[i] * 80 + qA[i] * 8)               = hv;             \
        *(uint2*)(sb + SPLIT_BYTES + rA[i] * 80 + qA[i] * 8) = lv;             \
    } }

    CPB(0, 0);
    LDG_A(0);
    STS_A(0);
    CP_WAIT0();
    __syncthreads();

    for (int c = 0; c < 16; c++) {
        int buf = c & 1;
        if (c < 15) {
            CPB(c + 1, buf ^ 1);
            LDG_A(c + 1);
        }

        uint32_t abase = sbase + buf * BUF_BYTES + aOff;
        uint32_t bbase = sbase + buf * BUF_BYTES + bOff;
#pragma unroll
        for (int kk = 0; kk < 2; kk++) {
            uint32_t kb = kk * 32;
            uint32_t fah[4][4], fbh[2][4];
#pragma unroll
            for (int mi = 0; mi < 4; mi++)
                ldsm4(fah[mi], abase + mi * 1280 + kb);
#pragma unroll
            for (int j2 = 0; j2 < 2; j2++)
                ldsm4(fbh[j2], bbase + j2 * 1280 + kb);
#pragma unroll
            for (int mi = 0; mi < 4; mi++)
#pragma unroll
                for (int nj = 0; nj < 4; nj++)
                    mma16816(acc[mi][nj], fah[mi],
                             fbh[nj >> 1][(nj & 1) * 2], fbh[nj >> 1][(nj & 1) * 2 + 1]);
            uint32_t fbl[2][4];
#pragma unroll
            for (int j2 = 0; j2 < 2; j2++)
                ldsm4(fbl[j2], bbase + SPLIT_BYTES + j2 * 1280 + kb);
#pragma unroll
            for (int mi = 0; mi < 4; mi++)
#pragma unroll
                for (int nj = 0; nj < 4; nj++)
                    mma16816(acc[mi][nj], fah[mi],
                             fbl[nj >> 1][(nj & 1) * 2], fbl[nj >> 1][(nj & 1) * 2 + 1]);
            uint32_t fal[4][4];
#pragma unroll
            for (int mi = 0; mi < 4; mi++)
                ldsm4(fal[mi], abase + SPLIT_BYTES + mi * 1280 + kb);
#pragma unroll
            for (int mi = 0; mi < 4; mi++)
#pragma unroll
                for (int nj = 0; nj < 4; nj++)
                    mma16816(acc[mi][nj], fal[mi],
                             fbh[nj >> 1][(nj & 1) * 2], fbh[nj >> 1][(nj & 1) * 2 + 1]);
        }

        if (c < 15) {
            STS_A(buf ^ 1);
            CP_WAIT0();
            __syncthreads();
        }
    }

#pragma unroll
    for (int mi = 0; mi < 4; mi++) {
        int row = bm * 128 + wm + mi * 16 + (l >> 2);
#pragma unroll
        for (int nj = 0; nj < 4; nj++) {
            int col = bn * 128 + wn + nj * 8 + 2 * (l & 3);
            float2 bv = *(const float2*)&bias[col];
            float2 v0 = make_float2(acc[mi][nj][0] + bv.x, acc[mi][nj][1] + bv.y);
            float2 v1 = make_float2(acc[mi][nj][2] + bv.x, acc[mi][nj][3] + bv.y);
            *(float2*)&g_gates[(size_t)row * G3 + col]       = v0;
            *(float2*)&g_gates[(size_t)(row + 8) * G3 + col] = v1;
        }
    }
}

// ---------------- mma.sync persistent scan (512 threads, 16 warps) ----------------
// 128 blocks (bx=bid&3: 32 batches; by=bid>>2: 16 hh).
// Warps: mw = wid>>3 (M half, 16 batches), kw = wid&7 (64-k split).
// Epilogue: 1 h value per thread (512 = 32b x 16hh).
#define HROWB   1040
#define A_HI    0
#define A_LO    33280
#define B_HI    66560
#define B_LO    116480
#define RED_OFF 166400
#define SCAN_SMEM (RED_OFF + 16 * 768 * 4)   // 215552

__global__ __launch_bounds__(512)
void scan_mma_kernel(const float* __restrict__ carry,
                     const void*  __restrict__ resets,
                     float* __restrict__ outputs,
                     float* __restrict__ carry_out) {
    extern __shared__ char smem[];
    uint32_t sbase = smem_u32(smem);

    int t = threadIdx.x, l = t & 31, wid = t >> 5;
    int kw = wid & 7, mw = wid >> 3;
    int bid = blockIdx.x;
    int bx = bid & 3, by = bid >> 2;
    int b0 = bx * 32;
    int hh0g = by * 16;
    int mode = g_reset_mode;

    const unsigned char* rbytes = (const unsigned char*)resets;
    const int*           rints  = (const int*)resets;

    // ---- one-time: W slices into smem ----
    {
        const char* wg = (const char*)g_Wh16;
#pragma unroll
        for (int sp = 0; sp < 2; sp++) {
            size_t gbase = ((size_t)sp * 32 + by) * 48 * DIN * 2;
#pragma unroll
            for (int i = 0; i < 6; i++) {
                int u = t + i * 512;                 // 3072 units of 16B per split
                int row = u >> 6, off = (u & 63) * 16;
                *(uint4*)(smem + B_HI + sp * 49920 + row * HROWB + off) =
                    *(const uint4*)(wg + gbase + (size_t)row * 1024 + off);
            }
        }
    }

    uint32_t aoff = sbase + A_HI +
        (uint32_t)((mw * 16 + (l & 7) + ((l >> 3) & 1) * 8) * HROWB + ((l >> 4) * 8) * 2);
    uint32_t boff = sbase + B_HI +
        (uint32_t)(((l & 7) + ((l >> 4) * 8)) * HROWB + (((l >> 3) & 1) * 8) * 2);

    // H staging: row = t>>4 (0..31), 64B chunk = (t&15)*64
    int srow = t >> 4, scoff = (t & 15) * 64;

    // epilogue identity: 1 value per thread
    int eb = t >> 4, ehh = t & 15;
    int gb = b0 + eb;
    int ghh = hh0g + ehh;
    int emw = eb >> 4, erow8 = (eb >> 3) & 1, erowl = eb & 7;
    int nt01 = ehh >> 3;
    int elane = erowl * 4 + ((ehh & 7) >> 1);
    int ecreg = erow8 * 2 + (ehh & 1);

    float hp = carry[(size_t)gb * HDIM + ghh];

    float* redf = (float*)(smem + RED_OFF);
    __syncthreads();   // W staged

    for (int s = 0; s < SEQ; s++) {
        int par = s & 1;

        size_t grow = ((size_t)s * BATCH + gb) * G3;
        float gz = g_gates[grow + ghh];
        float gr = g_gates[grow + HDIM + ghh];
        float gn = g_gates[grow + 2 * HDIM + ghh];
        bool ers = (mode == 0) ? (rints[s * BATCH + gb] != 0)
                               : (rbytes[s * BATCH + gb] != 0);
        float em = ers ? 0.f : 1.f;
        bool srs = (mode == 0) ? (rints[s * BATCH + b0 + srow] != 0)
                               : (rbytes[s * BATCH + b0 + srow] != 0);

        if (s > 0) {
            if (l == 0) {
                unsigned* cp = &g_done[(s - 1) * 4 + bx];
                while (ld_acq(cp) < 32u) { }
            }
            __syncwarp();
        }

        // ---- stage H (masked): 64B hi + 64B lo per thread ----
        {
            char* shi = smem + A_HI + srow * HROWB + scoff;
            char* slo = smem + A_LO + srow * HROWB + scoff;
            if (srs) {
                uint4 z = make_uint4(0, 0, 0, 0);
#pragma unroll
                for (int i = 0; i < 4; i++) {
                    *(uint4*)(shi + i * 16) = z;
                    *(uint4*)(slo + i * 16) = z;
                }
            } else if (s == 0) {
                const float* cp = carry + (size_t)(b0 + srow) * HDIM + (t & 15) * 32;
#pragma unroll
                for (int i = 0; i < 8; i++) {
                    float4 v = *(const float4*)(cp + i * 4);
                    __nv_bfloat16 h0, h1, h2, h3, l0, l1, l2, l3;
                    split1(v.x, h0, l0); split1(v.y, h1, l1);
                    split1(v.z, h2, l2); split1(v.w, h3, l3);
                    uint2 hv; hv.x = pack2(h0, h1); hv.y = pack2(h2, h3);
                    uint2 lv; lv.x = pack2(l0, l1); lv.y = pack2(l2, l3);
                    *(uint2*)(shi + i * 8) = hv;
                    *(uint2*)(slo + i * 8) = lv;
                }
            } else {
                const char* ghi = (const char*)&g_h16[par][0][(size_t)(b0 + srow) * HDIM] + scoff;
                const char* glo = (const char*)&g_h16[par][1][(size_t)(b0 + srow) * HDIM] + scoff;
#pragma unroll
                for (int i = 0; i < 4; i++) {
                    *(uint4*)(shi + i * 16) = *(const uint4*)(ghi + i * 16);
                    *(uint4*)(slo + i * 16) = *(const uint4*)(glo + i * 16);
                }
            }
        }
        __syncthreads();

        // ---- mma over this warp's 64-k (128B) range ----
        float acc[6][4];
#pragma unroll
        for (int i = 0; i < 6; i++)
#pragma unroll
            for (int j = 0; j < 4; j++) acc[i][j] = 0.f;

#pragma unroll
        for (int kt = 0; kt < 4; kt++) {
            uint32_t kb = (uint32_t)(kw * 128 + kt * 32);
            uint32_t fah[4], fal[4], fbh[3][4], fbl[3][4];
            ldsm4(fah, aoff + kb);
            ldsm4(fal, aoff + A_LO + kb);
#pragma unroll
            for (int j2 = 0; j2 < 3; j2++) {
                ldsm4(fbh[j2], boff + j2 * 16640 + kb);
                ldsm4(fbl[j2], boff + 49920 + j2 * 16640 + kb);
            }
#pragma unroll
            for (int j2 = 0; j2 < 3; j2++)
#pragma unroll
                for (int sub = 0; sub < 2; sub++) {
                    int nt = j2 * 2 + sub;
                    mma16816(acc[nt], fah, fbh[j2][sub * 2], fbh[j2][sub * 2 + 1]);
                    mma16816(acc[nt], fah, fbl[j2][sub * 2], fbl[j2][sub * 2 + 1]);
                    mma16816(acc[nt], fal, fbh[j2][sub * 2], fbh[j2][sub * 2 + 1]);
                }
        }

        // ---- cross-warp reduction via smem ----
        {
            float* rw = redf + wid * 768;
#pragma unroll
            for (int nt = 0; nt < 6; nt++)
#pragma unroll
                for (int c = 0; c < 4; c++)
                    rw[(nt * 4 + c) * 32 + l] = acc[nt][c];
        }
        __syncthreads();

        // ---- epilogue: 1 h value per thread ----
        float sz = 0.f, sr = 0.f, sn = 0.f;
#pragma unroll
        for (int kwp = 0; kwp < 8; kwp++) {
            const float* rb = redf + (emw * 8 + kwp) * 768;
            sz += rb[((0 * 2 + nt01) * 4 + ecreg) * 32 + elane];
            sr += rb[((1 * 2 + nt01) * 4 + ecreg) * 32 + elane];
            sn += rb[((2 * 2 + nt01) * 4 + ecreg) * 32 + elane];
        }
        float z = 1.f / (1.f + __expf(-(gz + sz)));
        float r = 1.f / (1.f + __expf(-(gr + sr)));
        float n = tanhf(gn + r * sn);
        float hn = (1.f - z) * n + z * (hp * em);
        hp = hn;

        outputs[((size_t)s * BATCH + gb) * HDIM + ghh] = hn;
        {
            __nv_bfloat16 h, lo;
            split1(hn, h, lo);
            g_h16[par ^ 1][0][(size_t)gb * HDIM + ghh] = h;
            g_h16[par ^ 1][1][(size_t)gb * HDIM + ghh] = lo;
        }
        if (carry_out && s == SEQ - 1)
            carry_out[(size_t)gb * HDIM + ghh] = hn;

        __syncthreads();
        if (t == 0 && s < SEQ - 1) red_rel(&g_done[s * 4 + bx]);
    }
}

// ---------------- launcher ----------------
extern "C" void kernel_launch(void* const* d_in, const int* in_sizes, int n_in,
                              void* d_out, int out_size) {
    const float* carry = (const float*)d_in[0];
    const float* ins   = (const float*)d_in[1];
    const void*  rsts  = d_in[2];
    const float* W_in  = (const float*)d_in[3];
    const float* b_in  = (const float*)d_in[4];
    const float* W_h   = (const float*)d_in[5];

    float* out = (float*)d_out;
    float* carry_out;
    float* outputs;
    if (out_size == (int)((size_t)SEQ * BATCH * HDIM)) {
        carry_out = nullptr;
        outputs   = out;
    } else {
        carry_out = out;
        outputs   = out + (size_t)BATCH * HDIM;
    }

    cudaFuncSetAttribute(gates_mma_kernel,
                         cudaFuncAttributeMaxDynamicSharedMemorySize, GEMM_SMEM);
    cudaFuncSetAttribute(scan_mma_kernel,
                         cudaFuncAttributeMaxDynamicSharedMemorySize, SCAN_SMEM);

    init_kernel<<<2, 256>>>((const unsigned int*)rsts);
    prep_w_kernel<<<(G3 * DIN + 255) / 256, 256>>>(W_in);
    prep_wh_kernel<<<(32 * 48 * DIN + 255) / 256, 256>>>(W_h);
    gates_mma_kernel<<<dim3(G3 / 128, MROWS / 128), 256, GEMM_SMEM>>>(ins, b_in);
    scan_mma_kernel<<<128, 512, SCAN_SMEM>>>(carry, rsts, outputs, carry_out);
}

// round 13
// speedup vs baseline: 3.1902x; 1.2140x over previous
#include <cuda_runtime.h>
#include <cuda_fp16.h>
#include <math.h>
#include <stdint.h>

#define SEQ   512
#define BATCH 128
#define DIN   512
#define HDIM  512
#define G3    1536
#define MROWS (SEQ * BATCH)        // 65536

// ---------------- scratch (device globals) ----------------
__device__ float g_gates[(size_t)SEQ * BATCH * G3];          // ~402MB
__device__ __half g_Bhi[(size_t)G3 * DIN];                   // W_in^T hi [n][k]
__device__ __half g_Blo[(size_t)G3 * DIN];                   // W_in^T lo [n][k]
__device__ __half g_Wh16[(size_t)2 * 32 * 48 * DIN];         // W_h split [split][by][c][k]
__device__ __half g_h16[2][(size_t)BATCH * HDIM];            // [parity][b*512+hh] (single fp16)
__device__ int      g_reset_mode;
__device__ unsigned g_done[SEQ * 4];                         // per-(step,bx) counters

// ---------------- mma.sync helpers ----------------
__device__ __forceinline__ uint32_t smem_u32(const void* p) {
    return (uint32_t)__cvta_generic_to_shared(p);
}
__device__ __forceinline__ void ldsm4(uint32_t* r, uint32_t addr) {
    asm volatile("ldmatrix.sync.aligned.m8n8.x4.shared.b16 {%0,%1,%2,%3}, [%4];"
                 : "=r"(r[0]), "=r"(r[1]), "=r"(r[2]), "=r"(r[3]) : "r"(addr));
}
__device__ __forceinline__ void mma16816(float* c, const uint32_t* a,
                                         uint32_t b0, uint32_t b1) {
    asm volatile(
        "mma.sync.aligned.m16n8k16.row.col.f32.f16.f16.f32 "
        "{%0,%1,%2,%3}, {%4,%5,%6,%7}, {%8,%9}, {%0,%1,%2,%3};"
        : "+f"(c[0]), "+f"(c[1]), "+f"(c[2]), "+f"(c[3])
        : "r"(a[0]), "r"(a[1]), "r"(a[2]), "r"(a[3]), "r"(b0), "r"(b1));
}
__device__ __forceinline__ unsigned ld_acq(const unsigned* p) {
    unsigned v;
    asm volatile("ld.acquire.gpu.global.u32 %0, [%1];" : "=r"(v) : "l"(p) : "memory");
    return v;
}
__device__ __forceinline__ void red_rel(unsigned* p) {
    asm volatile("red.release.gpu.global.add.u32 [%0], 1;" :: "l"(p) : "memory");
}
__device__ __forceinline__ void cp_async16(uint32_t saddr, const void* g) {
    asm volatile("cp.async.cg.shared.global [%0], [%1], 16;" :: "r"(saddr), "l"(g));
}
#define CP_COMMIT() asm volatile("cp.async.commit_group;" ::: "memory")
#define CP_WAIT0()  asm volatile("cp.async.wait_group 0;" ::: "memory")

// pack two fp16 into a uint32 (low = first)
__device__ __forceinline__ uint32_t pack2h(__half a, __half b) {
    __half2 v; v.x = a; v.y = b;
    return *(uint32_t*)&v;
}
// split one float into (hi, lo) fp16
__device__ __forceinline__ void split1h(float x, __half& h, __half& l) {
    h = __float2half(x);
    l = __float2half(x - __half2float(h));
}

// ---------------- init + reset dtype sniffing ----------------
__global__ void init_kernel(const unsigned int* __restrict__ r) {
    int t = blockIdx.x * 256 + threadIdx.x;
    for (int i = t; i < SEQ * 4; i += 512) g_done[i] = 0u;
    if (t == 0) {
        bool word_mode = true;
        for (int i = 0; i < 64; i++) {
            unsigned v = r[i];
            if (!(v == 0u || v == 1u || v == 0x3F800000u)) { word_mode = false; break; }
        }
        g_reset_mode = word_mode ? 0 : 2;
    }
}

// ---------------- prep kernels ----------------
__global__ void prep_w_kernel(const float* __restrict__ W) {
    int idx = blockIdx.x * 256 + threadIdx.x;
    if (idx < G3 * DIN) {
        int n = idx >> 9, k = idx & 511;
        float x = W[(size_t)k * G3 + n];
        __half h, l;
        split1h(x, h, l);
        g_Bhi[idx] = h;
        g_Blo[idx] = l;
    }
}
// W_h split: [split][by][c(0..47)][k];  c: 0-15 z, 16-31 r, 32-47 n; hh = by*16 + (c&15)
__global__ void prep_wh_kernel(const float* __restrict__ Wh) {
    int idx = blockIdx.x * 256 + threadIdx.x;   // over 32*48*512
    if (idx < 32 * 48 * DIN) {
        int k  = idx & 511;
        int c  = (idx >> 9) % 48;
        int by = idx / (48 * DIN);
        int j  = c >> 4;
        int hh = by * 16 + (c & 15);
        float x = Wh[(size_t)k * G3 + j * HDIM + hh];
        __half h, l;
        split1h(x, h, l);
        size_t o = ((size_t)by * 48 + c) * DIN + k;
        g_Wh16[o] = h;
        g_Wh16[(size_t)32 * 48 * DIN + o] = l;
    }
}

// ---------------- mma.sync gates GEMM (fp16 A single, B hi/lo; 2 products) ----------------
#define TROW 40
#define SPLIT_BYTES 10240
#define BUF_BYTES   30720            // A (1 split) + Bhi + Blo
#define GEMM_SMEM   (2 * BUF_BYTES)  // 60KB

__global__ __launch_bounds__(256, 2)
void gates_mma_kernel(const float* __restrict__ A,      // ins fp32 [65536][512]
                      const float* __restrict__ bias) {
    extern __shared__ char smem[];
    uint32_t sbase = smem_u32(smem);

    int t = threadIdx.x, l = t & 31, wid = t >> 5;
    int bn = blockIdx.x, bm = blockIdx.y;
    int wm = (wid & 1) * 64, wn = (wid >> 1) * 32;

    uint32_t aOff = ((wm + (l & 7) + ((l >> 3) & 1) * 8) * TROW + ((l >> 4) * 8)) * 2;
    uint32_t bOff = SPLIT_BYTES +
                    ((wn + (l & 7) + ((l >> 4) * 8)) * TROW + (((l >> 3) & 1) * 8)) * 2;

    int rA[4], qA[4];
#pragma unroll
    for (int i = 0; i < 4; i++) { int u = t + i * 256; rA[i] = u >> 3; qA[i] = u & 7; }
    int u0 = t, u1 = t + 256;
    int r0 = u0 >> 2, q0 = u0 & 3;
    int r1 = u1 >> 2, q1 = u1 & 3;

    const float*  Af = A     + (size_t)(bm * 128) * DIN;
    const __half* Bh = g_Bhi + (size_t)(bn * 128) * DIN;
    const __half* Bl = g_Blo + (size_t)(bn * 128) * DIN;

    float acc[4][4][4];
#pragma unroll
    for (int i = 0; i < 4; i++)
#pragma unroll
        for (int j = 0; j < 4; j++)
#pragma unroll
            for (int k = 0; k < 4; k++) acc[i][j][k] = 0.f;

    float4 ra[4];

#define LDG_A(kc) {                                                            \
    int k0 = (kc) * 32;                                                        \
    ra[0] = *(const float4*)(Af + (size_t)rA[0] * DIN + k0 + qA[0] * 4);       \
    ra[1] = *(const float4*)(Af + (size_t)rA[1] * DIN + k0 + qA[1] * 4);       \
    ra[2] = *(const float4*)(Af + (size_t)rA[2] * DIN + k0 + qA[2] * 4);       \
    ra[3] = *(const float4*)(Af + (size_t)rA[3] * DIN + k0 + qA[3] * 4); }

#define CPB(kc, buf) {                                                         \
    int k0 = (kc) * 32;                                                        \
    uint32_t sb = sbase + (buf) * BUF_BYTES;                                   \
    cp_async16(sb + SPLIT_BYTES + r0 * 80 + q0 * 16,                           \
               Bh + (size_t)r0 * DIN + k0 + q0 * 8);                           \
    cp_async16(sb + SPLIT_BYTES + r1 * 80 + q1 * 16,                           \
               Bh + (size_t)r1 * DIN + k0 + q1 * 8);                           \
    cp_async16(sb + 2 * SPLIT_BYTES + r0 * 80 + q0 * 16,                       \
               Bl + (size_t)r0 * DIN + k0 + q0 * 8);                           \
    cp_async16(sb + 2 * SPLIT_BYTES + r1 * 80 + q1 * 16,                       \
               Bl + (size_t)r1 * DIN + k0 + q1 * 8);                           \
    CP_COMMIT(); }

#define STS_A(buf) {                                                           \
    char* sb = smem + (buf) * BUF_BYTES;                                       \
    _Pragma("unroll")                                                          \
    for (int i = 0; i < 4; i++) {                                              \
        uint2 hv;                                                              \
        hv.x = pack2h(__float2half(ra[i].x), __float2half(ra[i].y));           \
        hv.y = pack2h(__float2half(ra[i].z), __float2half(ra[i].w));           \
        *(uint2*)(sb + rA[i] * 80 + qA[i] * 8) = hv;                           \
    } }

    CPB(0, 0);
    LDG_A(0);
    STS_A(0);
    CP_WAIT0();
    __syncthreads();

    for (int c = 0; c < 16; c++) {
        int buf = c & 1;
        if (c < 15) {
            CPB(c + 1, buf ^ 1);
            LDG_A(c + 1);
        }

        uint32_t abase = sbase + buf * BUF_BYTES + aOff;
        uint32_t bbase = sbase + buf * BUF_BYTES + bOff;
#pragma unroll
        for (int kk = 0; kk < 2; kk++) {
            uint32_t kb = kk * 32;
            uint32_t fah[4][4], fbh[2][4];
#pragma unroll
            for (int mi = 0; mi < 4; mi++)
                ldsm4(fah[mi], abase + mi * 1280 + kb);
#pragma unroll
            for (int j2 = 0; j2 < 2; j2++)
                ldsm4(fbh[j2], bbase + j2 * 1280 + kb);
#pragma unroll
            for (int mi = 0; mi < 4; mi++)
#pragma unroll
                for (int nj = 0; nj < 4; nj++)
                    mma16816(acc[mi][nj], fah[mi],
                             fbh[nj >> 1][(nj & 1) * 2], fbh[nj >> 1][(nj & 1) * 2 + 1]);
            uint32_t fbl[2][4];
#pragma unroll
            for (int j2 = 0; j2 < 2; j2++)
                ldsm4(fbl[j2], bbase + SPLIT_BYTES + j2 * 1280 + kb);
#pragma unroll
            for (int mi = 0; mi < 4; mi++)
#pragma unroll
                for (int nj = 0; nj < 4; nj++)
                    mma16816(acc[mi][nj], fah[mi],
                             fbl[nj >> 1][(nj & 1) * 2], fbl[nj >> 1][(nj & 1) * 2 + 1]);
        }

        if (c < 15) {
            STS_A(buf ^ 1);
            CP_WAIT0();
            __syncthreads();
        }
    }

#pragma unroll
    for (int mi = 0; mi < 4; mi++) {
        int row = bm * 128 + wm + mi * 16 + (l >> 2);
#pragma unroll
        for (int nj = 0; nj < 4; nj++) {
            int col = bn * 128 + wn + nj * 8 + 2 * (l & 3);
            float2 bv = *(const float2*)&bias[col];
            float2 v0 = make_float2(acc[mi][nj][0] + bv.x, acc[mi][nj][1] + bv.y);
            float2 v1 = make_float2(acc[mi][nj][2] + bv.x, acc[mi][nj][3] + bv.y);
            *(float2*)&g_gates[(size_t)row * G3 + col]       = v0;
            *(float2*)&g_gates[(size_t)(row + 8) * G3 + col] = v1;
        }
    }
}

// ---------------- mma.sync persistent scan (fp16 h single; 2 products) ----------------
// 128 blocks (bx=bid&3: 32 batches; by=bid>>2: 16 hh), 512 threads, 16 warps.
// Smem: A (H fp16) 32x1040; B_HI 48x1040; B_LO 48x1040; red 16x768 fp32.
#define HROWB   1040
#define A_HI    0
#define B_HI    33280
#define B_LO    83200
#define RED_OFF 133120
#define SCAN_SMEM (RED_OFF + 16 * 768 * 4)   // 182272

__global__ __launch_bounds__(512)
void scan_mma_kernel(const float* __restrict__ carry,
                     const void*  __restrict__ resets,
                     float* __restrict__ outputs,
                     float* __restrict__ carry_out) {
    extern __shared__ char smem[];
    uint32_t sbase = smem_u32(smem);

    int t = threadIdx.x, l = t & 31, wid = t >> 5;
    int kw = wid & 7, mw = wid >> 3;
    int bid = blockIdx.x;
    int bx = bid & 3, by = bid >> 2;
    int b0 = bx * 32;
    int hh0g = by * 16;
    int mode = g_reset_mode;

    const unsigned char* rbytes = (const unsigned char*)resets;
    const int*           rints  = (const int*)resets;

    // ---- one-time: W slices into smem ----
    {
        const char* wg = (const char*)g_Wh16;
#pragma unroll
        for (int sp = 0; sp < 2; sp++) {
            size_t gbase = ((size_t)sp * 32 + by) * 48 * DIN * 2;
#pragma unroll
            for (int i = 0; i < 6; i++) {
                int u = t + i * 512;                 // 3072 units of 16B per split
                int row = u >> 6, off = (u & 63) * 16;
                *(uint4*)(smem + B_HI + sp * 49920 + row * HROWB + off) =
                    *(const uint4*)(wg + gbase + (size_t)row * 1024 + off);
            }
        }
    }

    uint32_t aoff = sbase + A_HI +
        (uint32_t)((mw * 16 + (l & 7) + ((l >> 3) & 1) * 8) * HROWB + ((l >> 4) * 8) * 2);
    uint32_t boff = sbase + B_HI +
        (uint32_t)(((l & 7) + ((l >> 4) * 8)) * HROWB + (((l >> 3) & 1) * 8) * 2);

    // H staging: row = t>>4 (0..31), 64B chunk = (t&15)*64
    int srow = t >> 4, scoff = (t & 15) * 64;

    // epilogue identity: 1 value per thread
    int eb = t >> 4, ehh = t & 15;
    int gb = b0 + eb;
    int ghh = hh0g + ehh;
    int emw = eb >> 4, erow8 = (eb >> 3) & 1, erowl = eb & 7;
    int nt01 = ehh >> 3;
    int elane = erowl * 4 + ((ehh & 7) >> 1);
    int ecreg = erow8 * 2 + (ehh & 1);

    float hp = carry[(size_t)gb * HDIM + ghh];

    float* redf = (float*)(smem + RED_OFF);
    __syncthreads();   // W staged

    for (int s = 0; s < SEQ; s++) {
        int par = s & 1;

        size_t grow = ((size_t)s * BATCH + gb) * G3;
        float gz = g_gates[grow + ghh];
        float gr = g_gates[grow + HDIM + ghh];
        float gn = g_gates[grow + 2 * HDIM + ghh];
        bool ers = (mode == 0) ? (rints[s * BATCH + gb] != 0)
                               : (rbytes[s * BATCH + gb] != 0);
        float em = ers ? 0.f : 1.f;
        bool srs = (mode == 0) ? (rints[s * BATCH + b0 + srow] != 0)
                               : (rbytes[s * BATCH + b0 + srow] != 0);

        if (s > 0) {
            if (l == 0) {
                unsigned* cp = &g_done[(s - 1) * 4 + bx];
                while (ld_acq(cp) < 32u) { }
            }
            __syncwarp();
        }

        // ---- stage H (masked): 64B fp16 per thread ----
        {
            char* shi = smem + A_HI + srow * HROWB + scoff;
            if (srs) {
                uint4 z = make_uint4(0, 0, 0, 0);
#pragma unroll
                for (int i = 0; i < 4; i++) *(uint4*)(shi + i * 16) = z;
            } else if (s == 0) {
                const float* cp = carry + (size_t)(b0 + srow) * HDIM + (t & 15) * 32;
#pragma unroll
                for (int i = 0; i < 8; i++) {
                    float4 v = *(const float4*)(cp + i * 4);
                    uint2 hv;
                    hv.x = pack2h(__float2half(v.x), __float2half(v.y));
                    hv.y = pack2h(__float2half(v.z), __float2half(v.w));
                    *(uint2*)(shi + i * 8) = hv;
                }
            } else {
                const char* ghi = (const char*)&g_h16[par][(size_t)(b0 + srow) * HDIM] + scoff;
#pragma unroll
                for (int i = 0; i < 4; i++)
                    *(uint4*)(shi + i * 16) = *(const uint4*)(ghi + i * 16);
            }
        }
        __syncthreads();

        // ---- mma over this warp's 64-k (128B) range (2 products) ----
        float acc[6][4];
#pragma unroll
        for (int i = 0; i < 6; i++)
#pragma unroll
            for (int j = 0; j < 4; j++) acc[i][j] = 0.f;

#pragma unroll
        for (int kt = 0; kt < 4; kt++) {
            uint32_t kb = (uint32_t)(kw * 128 + kt * 32);
            uint32_t fah[4], fbh[3][4], fbl[3][4];
            ldsm4(fah, aoff + kb);
#pragma unroll
            for (int j2 = 0; j2 < 3; j2++) {
                ldsm4(fbh[j2], boff + j2 * 16640 + kb);
                ldsm4(fbl[j2], boff + 49920 + j2 * 16640 + kb);
            }
#pragma unroll
            for (int j2 = 0; j2 < 3; j2++)
#pragma unroll
                for (int sub = 0; sub < 2; sub++) {
                    int nt = j2 * 2 + sub;
                    mma16816(acc[nt], fah, fbh[j2][sub * 2], fbh[j2][sub * 2 + 1]);
                    mma16816(acc[nt], fah, fbl[j2][sub * 2], fbl[j2][sub * 2 + 1]);
                }
        }

        // ---- cross-warp reduction via smem ----
        {
            float* rw = redf + wid * 768;
#pragma unroll
            for (int nt = 0; nt < 6; nt++)
#pragma unroll
                for (int c = 0; c < 4; c++)
                    rw[(nt * 4 + c) * 32 + l] = acc[nt][c];
        }
        __syncthreads();

        // ---- epilogue: 1 h value per thread ----
        float sz = 0.f, sr = 0.f, sn = 0.f;
#pragma unroll
        for (int kwp = 0; kwp < 8; kwp++) {
            const float* rb = redf + (emw * 8 + kwp) * 768;
            sz += rb[((0 * 2 + nt01) * 4 + ecreg) * 32 + elane];
            sr += rb[((1 * 2 + nt01) * 4 + ecreg) * 32 + elane];
            sn += rb[((2 * 2 + nt01) * 4 + ecreg) * 32 + elane];
        }
        float z = 1.f / (1.f + __expf(-(gz + sz)));
        float r = 1.f / (1.f + __expf(-(gr + sr)));
        float n = tanhf(gn + r * sn);
        float hn = (1.f - z) * n + z * (hp * em);
        hp = hn;

        outputs[((size_t)s * BATCH + gb) * HDIM + ghh] = hn;
        g_h16[par ^ 1][(size_t)gb * HDIM + ghh] = __float2half(hn);
        if (carry_out && s == SEQ - 1)
            carry_out[(size_t)gb * HDIM + ghh] = hn;

        __syncthreads();
        if (t == 0 && s < SEQ - 1) red_rel(&g_done[s * 4 + bx]);
    }
}

// ---------------- launcher ----------------
extern "C" void kernel_launch(void* const* d_in, const int* in_sizes, int n_in,
                              void* d_out, int out_size) {
    const float* carry = (const float*)d_in[0];
    const float* ins   = (const float*)d_in[1];
    const void*  rsts  = d_in[2];
    const float* W_in  = (const float*)d_in[3];
    const float* b_in  = (const float*)d_in[4];
    const float* W_h   = (const float*)d_in[5];

    float* out = (float*)d_out;
    float* carry_out;
    float* outputs;
    if (out_size == (int)((size_t)SEQ * BATCH * HDIM)) {
        carry_out = nullptr;
        outputs   = out;
    } else {
        carry_out = out;
        outputs   = out + (size_t)BATCH * HDIM;
    }

    cudaFuncSetAttribute(gates_mma_kernel,
                         cudaFuncAttributeMaxDynamicSharedMemorySize, GEMM_SMEM);
    cudaFuncSetAttribute(scan_mma_kernel,
                         cudaFuncAttributeMaxDynamicSharedMemorySize, SCAN_SMEM);

    init_kernel<<<2, 256>>>((const unsigned int*)rsts);
    prep_w_kernel<<<(G3 * DIN + 255) / 256, 256>>>(W_in);
    prep_wh_kernel<<<(32 * 48 * DIN + 255) / 256, 256>>>(W_h);
    gates_mma_kernel<<<dim3(G3 / 128, MROWS / 128), 256, GEMM_SMEM>>>(ins, b_in);
    scan_mma_kernel<<<128, 512, SCAN_SMEM>>>(carry, rsts, outputs, carry_out);
}

// round 14
// speedup vs baseline: 3.7499x; 1.1754x over previous
#include <cuda_runtime.h>
#include <cuda_fp16.h>
#include <math.h>
#include <stdint.h>

#define SEQ   512
#define BATCH 128
#define DIN   512
#define HDIM  512
#define G3    1536
#define MROWS (SEQ * BATCH)        // 65536

// ---------------- scratch (device globals) ----------------
__device__ float g_gates[(size_t)SEQ * BATCH * G3];          // ~402MB
__device__ __half g_B[(size_t)G3 * DIN];                     // W_in^T fp16 [n][k]
__device__ __half g_Wh16[(size_t)32 * 48 * DIN];             // W_h fp16 [by][c][k]
__device__ __half g_h16[2][(size_t)BATCH * HDIM];            // [parity][b*512+hh]
__device__ int      g_reset_mode;
__device__ unsigned g_done[SEQ * 4];                         // per-(step,bx) counters

// ---------------- mma.sync helpers ----------------
__device__ __forceinline__ uint32_t smem_u32(const void* p) {
    return (uint32_t)__cvta_generic_to_shared(p);
}
__device__ __forceinline__ void ldsm4(uint32_t* r, uint32_t addr) {
    asm volatile("ldmatrix.sync.aligned.m8n8.x4.shared.b16 {%0,%1,%2,%3}, [%4];"
                 : "=r"(r[0]), "=r"(r[1]), "=r"(r[2]), "=r"(r[3]) : "r"(addr));
}
__device__ __forceinline__ void mma16816(float* c, const uint32_t* a,
                                         uint32_t b0, uint32_t b1) {
    asm volatile(
        "mma.sync.aligned.m16n8k16.row.col.f32.f16.f16.f32 "
        "{%0,%1,%2,%3}, {%4,%5,%6,%7}, {%8,%9}, {%0,%1,%2,%3};"
        : "+f"(c[0]), "+f"(c[1]), "+f"(c[2]), "+f"(c[3])
        : "r"(a[0]), "r"(a[1]), "r"(a[2]), "r"(a[3]), "r"(b0), "r"(b1));
}
__device__ __forceinline__ unsigned ld_acq(const unsigned* p) {
    unsigned v;
    asm volatile("ld.acquire.gpu.global.u32 %0, [%1];" : "=r"(v) : "l"(p) : "memory");
    return v;
}
__device__ __forceinline__ void red_rel(unsigned* p) {
    asm volatile("red.release.gpu.global.add.u32 [%0], 1;" :: "l"(p) : "memory");
}
__device__ __forceinline__ void cp_async16(uint32_t saddr, const void* g) {
    asm volatile("cp.async.cg.shared.global [%0], [%1], 16;" :: "r"(saddr), "l"(g));
}
#define CP_COMMIT() asm volatile("cp.async.commit_group;" ::: "memory")
#define CP_WAIT0()  asm volatile("cp.async.wait_group 0;" ::: "memory")

// pack two fp16 into a uint32 (low = first)
__device__ __forceinline__ uint32_t pack2h(__half a, __half b) {
    __half2 v; v.x = a; v.y = b;
    return *(uint32_t*)&v;
}

// ---------------- init + reset dtype sniffing ----------------
__global__ void init_kernel(const unsigned int* __restrict__ r) {
    int t = blockIdx.x * 256 + threadIdx.x;
    for (int i = t; i < SEQ * 4; i += 512) g_done[i] = 0u;
    if (t == 0) {
        bool word_mode = true;
        for (int i = 0; i < 64; i++) {
            unsigned v = r[i];
            if (!(v == 0u || v == 1u || v == 0x3F800000u)) { word_mode = false; break; }
        }
        g_reset_mode = word_mode ? 0 : 2;
    }
}

// ---------------- prep kernels ----------------
__global__ void prep_w_kernel(const float* __restrict__ W) {
    int idx = blockIdx.x * 256 + threadIdx.x;
    if (idx < G3 * DIN) {
        int n = idx >> 9, k = idx & 511;
        g_B[idx] = __float2half(W[(size_t)k * G3 + n]);
    }
}
// W_h: [by][c(0..47)][k];  c: 0-15 z, 16-31 r, 32-47 n; hh = by*16 + (c&15)
__global__ void prep_wh_kernel(const float* __restrict__ Wh) {
    int idx = blockIdx.x * 256 + threadIdx.x;   // over 32*48*512
    if (idx < 32 * 48 * DIN) {
        int k  = idx & 511;
        int c  = (idx >> 9) % 48;
        int by = idx / (48 * DIN);
        int j  = c >> 4;
        int hh = by * 16 + (c & 15);
        g_Wh16[idx] = __float2half(Wh[(size_t)k * G3 + j * HDIM + hh]);
    }
}

// ---------------- mma.sync gates GEMM (pure fp16, 1 product) ----------------
#define TROW 40
#define SPLIT_BYTES 10240
#define BUF_BYTES   20480            // A + B
#define GEMM_SMEM   (2 * BUF_BYTES)  // 40KB

__global__ __launch_bounds__(256, 2)
void gates_mma_kernel(const float* __restrict__ A,      // ins fp32 [65536][512]
                      const float* __restrict__ bias) {
    extern __shared__ char smem[];
    uint32_t sbase = smem_u32(smem);

    int t = threadIdx.x, l = t & 31, wid = t >> 5;
    int bn = blockIdx.x, bm = blockIdx.y;
    int wm = (wid & 1) * 64, wn = (wid >> 1) * 32;

    uint32_t aOff = ((wm + (l & 7) + ((l >> 3) & 1) * 8) * TROW + ((l >> 4) * 8)) * 2;
    uint32_t bOff = SPLIT_BYTES +
                    ((wn + (l & 7) + ((l >> 4) * 8)) * TROW + (((l >> 3) & 1) * 8)) * 2;

    int rA[4], qA[4];
#pragma unroll
    for (int i = 0; i < 4; i++) { int u = t + i * 256; rA[i] = u >> 3; qA[i] = u & 7; }
    int u0 = t, u1 = t + 256;
    int r0 = u0 >> 2, q0 = u0 & 3;
    int r1 = u1 >> 2, q1 = u1 & 3;

    const float*  Af = A   + (size_t)(bm * 128) * DIN;
    const __half* Bp = g_B + (size_t)(bn * 128) * DIN;

    float acc[4][4][4];
#pragma unroll
    for (int i = 0; i < 4; i++)
#pragma unroll
        for (int j = 0; j < 4; j++)
#pragma unroll
            for (int k = 0; k < 4; k++) acc[i][j][k] = 0.f;

    float4 ra[4];

#define LDG_A(kc) {                                                            \
    int k0 = (kc) * 32;                                                        \
    ra[0] = *(const float4*)(Af + (size_t)rA[0] * DIN + k0 + qA[0] * 4);       \
    ra[1] = *(const float4*)(Af + (size_t)rA[1] * DIN + k0 + qA[1] * 4);       \
    ra[2] = *(const float4*)(Af + (size_t)rA[2] * DIN + k0 + qA[2] * 4);       \
    ra[3] = *(const float4*)(Af + (size_t)rA[3] * DIN + k0 + qA[3] * 4); }

#define CPB(kc, buf) {                                                         \
    int k0 = (kc) * 32;                                                        \
    uint32_t sb = sbase + (buf) * BUF_BYTES;                                   \
    cp_async16(sb + SPLIT_BYTES + r0 * 80 + q0 * 16,                           \
               Bp + (size_t)r0 * DIN + k0 + q0 * 8);                           \
    cp_async16(sb + SPLIT_BYTES + r1 * 80 + q1 * 16,                           \
               Bp + (size_t)r1 * DIN + k0 + q1 * 8);                           \
    CP_COMMIT(); }

#define STS_A(buf) {                                                           \
    char* sb = smem + (buf) * BUF_BYTES;                                       \
    _Pragma("unroll")                                                          \
    for (int i = 0; i < 4; i++) {                                              \
        uint2 hv;                                                              \
        hv.x = pack2h(__float2half(ra[i].x), __float2half(ra[i].y));           \
        hv.y = pack2h(__float2half(ra[i].z), __float2half(ra[i].w));           \
        *(uint2*)(sb + rA[i] * 80 + qA[i] * 8) = hv;                           \
    } }

    CPB(0, 0);
    LDG_A(0);
    STS_A(0);
    CP_WAIT0();
    __syncthreads();

    for (int c = 0; c < 16; c++) {
        int buf = c & 1;
        if (c < 15) {
            CPB(c + 1, buf ^ 1);
            LDG_A(c + 1);
        }

        uint32_t abase = sbase + buf * BUF_BYTES + aOff;
        uint32_t bbase = sbase + buf * BUF_BYTES + bOff;
#pragma unroll
        for (int kk = 0; kk < 2; kk++) {
            uint32_t kb = kk * 32;
            uint32_t fah[4][4], fbh[2][4];
#pragma unroll
            for (int mi = 0; mi < 4; mi++)
                ldsm4(fah[mi], abase + mi * 1280 + kb);
#pragma unroll
            for (int j2 = 0; j2 < 2; j2++)
                ldsm4(fbh[j2], bbase + j2 * 1280 + kb);
#pragma unroll
            for (int mi = 0; mi < 4; mi++)
#pragma unroll
                for (int nj = 0; nj < 4; nj++)
                    mma16816(acc[mi][nj], fah[mi],
                             fbh[nj >> 1][(nj & 1) * 2], fbh[nj >> 1][(nj & 1) * 2 + 1]);
        }

        if (c < 15) {
            STS_A(buf ^ 1);
            CP_WAIT0();
            __syncthreads();
        }
    }

#pragma unroll
    for (int mi = 0; mi < 4; mi++) {
        int row = bm * 128 + wm + mi * 16 + (l >> 2);
#pragma unroll
        for (int nj = 0; nj < 4; nj++) {
            int col = bn * 128 + wn + nj * 8 + 2 * (l & 3);
            float2 bv = *(const float2*)&bias[col];
            float2 v0 = make_float2(acc[mi][nj][0] + bv.x, acc[mi][nj][1] + bv.y);
            float2 v1 = make_float2(acc[mi][nj][2] + bv.x, acc[mi][nj][3] + bv.y);
            *(float2*)&g_gates[(size_t)row * G3 + col]       = v0;
            *(float2*)&g_gates[(size_t)(row + 8) * G3 + col] = v1;
        }
    }
}

// ---------------- mma.sync persistent scan (pure fp16, 1 product) ----------------
// 128 blocks (bx=bid&3: 32 batches; by=bid>>2: 16 hh), 512 threads, 16 warps.
// Smem: A (H fp16) 32x1040; B (W fp16) 48x1040; red 16x768 fp32.
#define HROWB   1040
#define A_HI    0
#define B_OFF   33280
#define RED_OFF 83200
#define SCAN_SMEM (RED_OFF + 16 * 768 * 4)   // 132352

__global__ __launch_bounds__(512)
void scan_mma_kernel(const float* __restrict__ carry,
                     const void*  __restrict__ resets,
                     float* __restrict__ outputs,
                     float* __restrict__ carry_out) {
    extern __shared__ char smem[];
    uint32_t sbase = smem_u32(smem);

    int t = threadIdx.x, l = t & 31, wid = t >> 5;
    int kw = wid & 7, mw = wid >> 3;
    int bid = blockIdx.x;
    int bx = bid & 3, by = bid >> 2;
    int b0 = bx * 32;
    int hh0g = by * 16;
    int mode = g_reset_mode;

    const unsigned char* rbytes = (const unsigned char*)resets;
    const int*           rints  = (const int*)resets;

    // ---- one-time: W slice into smem (48 rows x 1024B) ----
    {
        const char* wg = (const char*)g_Wh16 + (size_t)by * 48 * DIN * 2;
#pragma unroll
        for (int i = 0; i < 6; i++) {
            int u = t + i * 512;                 // 3072 units of 16B
            int row = u >> 6, off = (u & 63) * 16;
            *(uint4*)(smem + B_OFF + row * HROWB + off) =
                *(const uint4*)(wg + (size_t)row * 1024 + off);
        }
    }

    uint32_t aoff = sbase + A_HI +
        (uint32_t)((mw * 16 + (l & 7) + ((l >> 3) & 1) * 8) * HROWB + ((l >> 4) * 8) * 2);
    uint32_t boff = sbase + B_OFF +
        (uint32_t)(((l & 7) + ((l >> 4) * 8)) * HROWB + (((l >> 3) & 1) * 8) * 2);

    // H staging: row = t>>4 (0..31), 64B chunk = (t&15)*64
    int srow = t >> 4, scoff = (t & 15) * 64;

    // epilogue identity: 1 value per thread
    int eb = t >> 4, ehh = t & 15;
    int gb = b0 + eb;
    int ghh = hh0g + ehh;
    int emw = eb >> 4, erow8 = (eb >> 3) & 1, erowl = eb & 7;
    int nt01 = ehh >> 3;
    int elane = erowl * 4 + ((ehh & 7) >> 1);
    int ecreg = erow8 * 2 + (ehh & 1);

    float hp = carry[(size_t)gb * HDIM + ghh];

    float* redf = (float*)(smem + RED_OFF);
    __syncthreads();   // W staged

    for (int s = 0; s < SEQ; s++) {
        int par = s & 1;

        size_t grow = ((size_t)s * BATCH + gb) * G3;
        float gz = g_gates[grow + ghh];
        float gr = g_gates[grow + HDIM + ghh];
        float gn = g_gates[grow + 2 * HDIM + ghh];
        bool ers = (mode == 0) ? (rints[s * BATCH + gb] != 0)
                               : (rbytes[s * BATCH + gb] != 0);
        float em = ers ? 0.f : 1.f;
        bool srs = (mode == 0) ? (rints[s * BATCH + b0 + srow] != 0)
                               : (rbytes[s * BATCH + b0 + srow] != 0);

        if (s > 0) {
            if (l == 0) {
                unsigned* cp = &g_done[(s - 1) * 4 + bx];
                while (ld_acq(cp) < 32u) { }
            }
            __syncwarp();
        }

        // ---- stage H (masked): 64B fp16 per thread ----
        {
            char* shi = smem + A_HI + srow * HROWB + scoff;
            if (srs) {
                uint4 z = make_uint4(0, 0, 0, 0);
#pragma unroll
                for (int i = 0; i < 4; i++) *(uint4*)(shi + i * 16) = z;
            } else if (s == 0) {
                const float* cp = carry + (size_t)(b0 + srow) * HDIM + (t & 15) * 32;
#pragma unroll
                for (int i = 0; i < 8; i++) {
                    float4 v = *(const float4*)(cp + i * 4);
                    uint2 hv;
                    hv.x = pack2h(__float2half(v.x), __float2half(v.y));
                    hv.y = pack2h(__float2half(v.z), __float2half(v.w));
                    *(uint2*)(shi + i * 8) = hv;
                }
            } else {
                const char* ghi = (const char*)&g_h16[par][(size_t)(b0 + srow) * HDIM] + scoff;
#pragma unroll
                for (int i = 0; i < 4; i++)
                    *(uint4*)(shi + i * 16) = *(const uint4*)(ghi + i * 16);
            }
        }
        __syncthreads();

        // ---- mma over this warp's 64-k (128B) range (1 product) ----
        float acc[6][4];
#pragma unroll
        for (int i = 0; i < 6; i++)
#pragma unroll
            for (int j = 0; j < 4; j++) acc[i][j] = 0.f;

#pragma unroll
        for (int kt = 0; kt < 4; kt++) {
            uint32_t kb = (uint32_t)(kw * 128 + kt * 32);
            uint32_t fah[4], fbh[3][4];
            ldsm4(fah, aoff + kb);
#pragma unroll
            for (int j2 = 0; j2 < 3; j2++)
                ldsm4(fbh[j2], boff + j2 * 16640 + kb);
#pragma unroll
            for (int j2 = 0; j2 < 3; j2++)
#pragma unroll
                for (int sub = 0; sub < 2; sub++) {
                    int nt = j2 * 2 + sub;
                    mma16816(acc[nt], fah, fbh[j2][sub * 2], fbh[j2][sub * 2 + 1]);
                }
        }

        // ---- cross-warp reduction via smem ----
        {
            float* rw = redf + wid * 768;
#pragma unroll
            for (int nt = 0; nt < 6; nt++)
#pragma unroll
                for (int c = 0; c < 4; c++)
                    rw[(nt * 4 + c) * 32 + l] = acc[nt][c];
        }
        __syncthreads();

        // ---- epilogue: 1 h value per thread ----
        float sz = 0.f, sr = 0.f, sn = 0.f;
#pragma unroll
        for (int kwp = 0; kwp < 8; kwp++) {
            const float* rb = redf + (emw * 8 + kwp) * 768;
            sz += rb[((0 * 2 + nt01) * 4 + ecreg) * 32 + elane];
            sr += rb[((1 * 2 + nt01) * 4 + ecreg) * 32 + elane];
            sn += rb[((2 * 2 + nt01) * 4 + ecreg) * 32 + elane];
        }
        float z = 1.f / (1.f + __expf(-(gz + sz)));
        float r = 1.f / (1.f + __expf(-(gr + sr)));
        float n = tanhf(gn + r * sn);
        float hn = (1.f - z) * n + z * (hp * em);
        hp = hn;

        outputs[((size_t)s * BATCH + gb) * HDIM + ghh] = hn;
        g_h16[par ^ 1][(size_t)gb * HDIM + ghh] = __float2half(hn);
        if (carry_out && s == SEQ - 1)
            carry_out[(size_t)gb * HDIM + ghh] = hn;

        __syncthreads();
        if (t == 0 && s < SEQ - 1) red_rel(&g_done[s * 4 + bx]);
    }
}

// ---------------- launcher ----------------
extern "C" void kernel_launch(void* const* d_in, const int* in_sizes, int n_in,
                              void* d_out, int out_size) {
    const float* carry = (const float*)d_in[0];
    const float* ins   = (const float*)d_in[1];
    const void*  rsts  = d_in[2];
    const float* W_in  = (const float*)d_in[3];
    const float* b_in  = (const float*)d_in[4];
    const float* W_h   = (const float*)d_in[5];

    float* out = (float*)d_out;
    float* carry_out;
    float* outputs;
    if (out_size == (int)((size_t)SEQ * BATCH * HDIM)) {
        carry_out = nullptr;
        outputs   = out;
    } else {
        carry_out = out;
        outputs   = out + (size_t)BATCH * HDIM;
    }

    cudaFuncSetAttribute(gates_mma_kernel,
                         cudaFuncAttributeMaxDynamicSharedMemorySize, GEMM_SMEM);
    cudaFuncSetAttribute(scan_mma_kernel,
                         cudaFuncAttributeMaxDynamicSharedMemorySize, SCAN_SMEM);

    init_kernel<<<2, 256>>>((const unsigned int*)rsts);
    prep_w_kernel<<<(G3 * DIN + 255) / 256, 256>>>(W_in);
    prep_wh_kernel<<<(32 * 48 * DIN + 255) / 256, 256>>>(W_h);
    gates_mma_kernel<<<dim3(G3 / 128, MROWS / 128), 256, GEMM_SMEM>>>(ins, b_in);
    scan_mma_kernel<<<128, 512, SCAN_SMEM>>>(carry, rsts, outputs, carry_out);
}